// round 10
// baseline (speedup 1.0000x reference)
#include <cuda_runtime.h>
#include <cuda_bf16.h>
#include <stdint.h>
#include <math.h>

#define S   2048
#define DIN 256
#define DM  512
#define NB  4
#define H   8
#define DK  64
#define BH  32
#define PAD 72

__device__ __nv_bfloat16 g_Qc[(size_t)BH * S * 128];   // [n][s][hi(64)|lo(64)]
__device__ __nv_bfloat16 g_Kc[(size_t)BH * S * 128];
__device__ __nv_bfloat16 g_Vhi[(size_t)BH * DK * S];   // [n][c][s]
__device__ __nv_bfloat16 g_Vlo[(size_t)BH * DK * S];
__device__ float g_inv[(size_t)BH * S];
__device__ float g_AO[(size_t)NB * S * DM];
__device__ float g_scratch[(size_t)NB * H * S * S];

__device__ __forceinline__ uint32_t smem_u32(const void* p) {
    uint32_t a;
    asm("{ .reg .u64 t; cvta.to.shared.u64 t, %1; cvt.u32.u64 %0, t; }" : "=r"(a) : "l"(p));
    return a;
}
__device__ __forceinline__ void ldsm4(uint32_t addr, uint32_t& r0, uint32_t& r1,
                                      uint32_t& r2, uint32_t& r3) {
    asm volatile("ldmatrix.sync.aligned.m8n8.x4.shared.b16 {%0,%1,%2,%3}, [%4];"
                 : "=r"(r0), "=r"(r1), "=r"(r2), "=r"(r3) : "r"(addr));
}
__device__ __forceinline__ void mma16816(float* c, const uint32_t* a, uint32_t b0, uint32_t b1) {
    asm volatile(
        "mma.sync.aligned.m16n8k16.row.col.f32.bf16.bf16.f32 "
        "{%0,%1,%2,%3},{%4,%5,%6,%7},{%8,%9},{%0,%1,%2,%3};"
        : "+f"(c[0]), "+f"(c[1]), "+f"(c[2]), "+f"(c[3])
        : "r"(a[0]), "r"(a[1]), "r"(a[2]), "r"(a[3]), "r"(b0), "r"(b1));
}
__device__ __forceinline__ void cp16(uint32_t s, const void* g) {
    asm volatile("cp.async.cg.shared.global [%0], [%1], 16;" :: "r"(s), "l"(g));
}
#define CP_COMMIT() asm volatile("cp.async.commit_group;" ::: "memory")
#define CP_WAIT0()  asm volatile("cp.async.wait_group 0;" ::: "memory")

// ---------------------------------------------------------------------------
// K1: QKV projection (fp32 SIMT) + bf16 hi/lo emission
// ---------------------------------------------------------------------------
__global__ __launch_bounds__(256) void qkv_kernel(
    const float* __restrict__ x,
    const float* __restrict__ Wq, const float* __restrict__ bq,
    const float* __restrict__ Wk, const float* __restrict__ bk,
    const float* __restrict__ Wv, const float* __restrict__ bv)
{
    const int s0 = blockIdx.x * 64, m0 = blockIdx.y * 64, b = blockIdx.z;
    __shared__ float sX[16][64];
    __shared__ float sW[3][64][16];
    const int tid = threadIdx.x, tx = tid & 15, ty = tid >> 4;
    float acc[3][4][4];
#pragma unroll
    for (int w = 0; w < 3; w++)
#pragma unroll
        for (int i = 0; i < 4; i++)
#pragma unroll
            for (int j = 0; j < 4; j++) acc[w][i][j] = 0.f;

    for (int d0 = 0; d0 < DIN; d0 += 16) {
        {
            int dd = tid >> 4, sv = (tid & 15) * 4;
            *(float4*)&sX[dd][sv] = *(const float4*)(x + (size_t)(b * DIN + d0 + dd) * S + s0 + sv);
        }
        {
            int mm = tid >> 2, dv = (tid & 3) * 4;
            const int wofs = (m0 + mm) * DIN + d0 + dv;
            *(float4*)&sW[0][mm][dv] = *(const float4*)(Wq + wofs);
            *(float4*)&sW[1][mm][dv] = *(const float4*)(Wk + wofs);
            *(float4*)&sW[2][mm][dv] = *(const float4*)(Wv + wofs);
        }
        __syncthreads();
#pragma unroll
        for (int dd = 0; dd < 16; dd++) {
            float xb[4];
            *(float4*)xb = *(float4*)&sX[dd][tx * 4];
#pragma unroll
            for (int w = 0; w < 3; w++) {
                float wr[4];
#pragma unroll
                for (int i = 0; i < 4; i++) wr[i] = sW[w][ty * 4 + i][dd];
#pragma unroll
                for (int i = 0; i < 4; i++)
#pragma unroll
                    for (int j = 0; j < 4; j++) acc[w][i][j] += wr[i] * xb[j];
            }
        }
        __syncthreads();
    }

    const int n = b * 8 + (m0 >> 6);
    const float* bs[3] = {bq, bk, bv};
#pragma unroll
    for (int w = 0; w < 3; w++) {
        float v[4][4];
#pragma unroll
        for (int i = 0; i < 4; i++) {
            float bb = bs[w][m0 + ty * 4 + i];
#pragma unroll
            for (int j = 0; j < 4; j++) v[i][j] = acc[w][i][j] + bb;
        }
        if (w < 2) {
            __nv_bfloat16* dst = (w == 0) ? g_Qc : g_Kc;
#pragma unroll
            for (int j = 0; j < 4; j++) {
                __align__(8) __nv_bfloat16 hi[4], lo[4];
#pragma unroll
                for (int i = 0; i < 4; i++) {
                    float p = v[i][j];
                    hi[i] = __float2bfloat16(p);
                    lo[i] = __float2bfloat16(p - __bfloat162float(hi[i]));
                }
                size_t off = ((size_t)n * S + s0 + tx * 4 + j) * 128 + ty * 4;
                *(uint2*)(dst + off) = *(uint2*)hi;
                *(uint2*)(dst + off + 64) = *(uint2*)lo;
            }
        } else {
#pragma unroll
            for (int i = 0; i < 4; i++) {
                __align__(8) __nv_bfloat16 hi[4], lo[4];
#pragma unroll
                for (int j = 0; j < 4; j++) {
                    float p = v[i][j];
                    hi[j] = __float2bfloat16(p);
                    lo[j] = __float2bfloat16(p - __bfloat162float(hi[j]));
                }
                size_t off = ((size_t)n * DK + ty * 4 + i) * S + s0 + tx * 4;
                *(uint2*)(g_Vhi + off) = *(uint2*)hi;
                *(uint2*)(g_Vlo + off) = *(uint2*)lo;
            }
        }
    }
}

// ---------------------------------------------------------------------------
// K2 (fused, pipelined, Q in SMEM): per (n, q-tile 128), 32 k-chunks of 64:
//   [wait K/V(kt); sync] -> issue K/V(kt+1) -> QK MMA -> exp/rowsum -> P smem
//   -> sync -> AV MMA.  E never hits DRAM.
// ---------------------------------------------------------------------------
__global__ __launch_bounds__(256) void fused_kernel()
{
    extern __shared__ __nv_bfloat16 smb[];
    __nv_bfloat16* sQh = smb;                  // [128][PAD]
    __nv_bfloat16* sQl = smb + 128 * PAD;
    __nv_bfloat16* sPh = smb + 256 * PAD;      // [128][PAD]
    __nv_bfloat16* sPl = smb + 384 * PAD;
    __nv_bfloat16* sKb = smb + 512 * PAD;      // 2 bufs x (Kh[64]+Kl[64]) rows
    __nv_bfloat16* sVb = smb + 768 * PAD;      // 2 bufs x (Vh[64]+Vl[64]) rows
    __shared__ float sRS[128][2];
    const int qb = blockIdx.x * 128, n = blockIdx.y;
    const int tid = threadIdx.x, wid = tid >> 5, lane = tid & 31;
    const int wm = wid >> 1, wn = wid & 1;
    const int g = lane >> 2, c = lane & 3;

    const __nv_bfloat16* Qg = g_Qc + ((size_t)n * S + qb) * 128;
    const __nv_bfloat16* Kg = g_Kc + (size_t)n * S * 128;
    const __nv_bfloat16* Vh = g_Vhi + (size_t)n * DK * S;
    const __nv_bfloat16* Vl = g_Vlo + (size_t)n * DK * S;

    const uint32_t uQh = smem_u32(sQh), uQl = smem_u32(sQl);
    const uint32_t uPh = smem_u32(sPh), uPl = smem_u32(sPl);
    const int arow = wm * 32 + (lane & 15);
    const int acol8 = (lane >> 4) << 3;
    const int brow = wn * 32 + (lane & 7) + ((lane >> 4) << 3);
    const int bcol8 = ((lane >> 3) & 1) << 3;

    // ---- prologue: Q (persistent) + K/V chunk 0 into buffer 0, one group ----
    for (int u = tid; u < 2048; u += 256) {
        int row = u >> 4, ch = u & 15;
        cp16(smem_u32((ch < 8 ? sQh : sQl) + row * PAD + (ch & 7) * 8),
             Qg + row * 128 + ch * 8);
    }
    for (int u = tid; u < 1024; u += 256) {
        int r = u >> 4, ch = u & 15;
        cp16(smem_u32(sKb + (ch < 8 ? 0 : 64 * PAD) + r * PAD + (ch & 7) * 8),
             Kg + (size_t)r * 128 + ch * 8);
    }
    for (int u = tid; u < 1024; u += 256) {
        int tier = u >> 9, cc = (u >> 3) & 63, ch = u & 7;
        cp16(smem_u32(sVb + tier * 64 * PAD + cc * PAD + ch * 8),
             (tier ? Vl : Vh) + (size_t)cc * S + ch * 8);
    }
    CP_COMMIT();

    float accO[8][4];
#pragma unroll
    for (int f = 0; f < 8; f++)
#pragma unroll
        for (int e = 0; e < 4; e++) accO[f][e] = 0.f;
    float rs[4] = {0.f, 0.f, 0.f, 0.f};

    for (int kt = 0; kt < 32; kt++) {
        const int buf = kt & 1;
        const uint32_t uKh = smem_u32(sKb + buf * 128 * PAD);
        const uint32_t uKl = uKh + 64 * PAD * 2;
        const uint32_t uVh = smem_u32(sVb + buf * 128 * PAD);
        const uint32_t uVl = uVh + 64 * PAD * 2;

        CP_WAIT0();
        __syncthreads();   // K/V(kt) [+Q on kt=0] visible; AV(kt-1) readers done

        if (kt < 31) {     // prefetch kt+1 into other buffer (overlaps whole iter)
            const int kb1 = (kt + 1) * 64, nb = buf ^ 1;
            __nv_bfloat16* nK = sKb + nb * 128 * PAD;
            __nv_bfloat16* nV = sVb + nb * 128 * PAD;
            for (int u = tid; u < 1024; u += 256) {
                int r = u >> 4, ch = u & 15;
                cp16(smem_u32(nK + (ch < 8 ? 0 : 64 * PAD) + r * PAD + (ch & 7) * 8),
                     Kg + (size_t)(kb1 + r) * 128 + ch * 8);
            }
            for (int u = tid; u < 1024; u += 256) {
                int tier = u >> 9, cc = (u >> 3) & 63, ch = u & 7;
                cp16(smem_u32(nV + tier * 64 * PAD + cc * PAD + ch * 8),
                     (tier ? Vl : Vh) + (size_t)cc * S + kb1 + ch * 8);
            }
            CP_COMMIT();
        }

        // ---- QK: M=128q, N=64k, contraction c=64 (Q from SMEM) ----
        float acc2[8][4];
#pragma unroll
        for (int f = 0; f < 8; f++)
#pragma unroll
            for (int e = 0; e < 4; e++) acc2[f][e] = 0.f;
#pragma unroll
        for (int ks = 0; ks < 4; ks++) {
            const int k0 = ks * 16;
            uint32_t ah[2][4], al[2][4];
#pragma unroll
            for (int mf = 0; mf < 2; mf++) {
                uint32_t off = (uint32_t)((arow + mf * 16) * PAD + k0 + acol8) * 2;
                ldsm4(uQh + off, ah[mf][0], ah[mf][1], ah[mf][2], ah[mf][3]);
                ldsm4(uQl + off, al[mf][0], al[mf][1], al[mf][2], al[mf][3]);
            }
#pragma unroll
            for (int nf2 = 0; nf2 < 2; nf2++) {
                uint32_t boff = (uint32_t)((brow + nf2 * 16) * PAD + k0 + bcol8) * 2;
                uint32_t bh[4], bl[4];
                ldsm4(uKh + boff, bh[0], bh[1], bh[2], bh[3]);
                ldsm4(uKl + boff, bl[0], bl[1], bl[2], bl[3]);
#pragma unroll
                for (int mf = 0; mf < 2; mf++) {
                    float* c0 = acc2[mf * 4 + nf2 * 2];
                    float* c1 = acc2[mf * 4 + nf2 * 2 + 1];
                    mma16816(c0, ah[mf], bh[0], bh[1]);
                    mma16816(c0, al[mf], bh[0], bh[1]);
                    mma16816(c0, ah[mf], bl[0], bl[1]);
                    mma16816(c1, ah[mf], bh[2], bh[3]);
                    mma16816(c1, al[mf], bh[2], bh[3]);
                    mma16816(c1, ah[mf], bl[2], bl[3]);
                }
            }
        }

        // ---- exp + rowsum + P hi/lo into SMEM ----
#pragma unroll
        for (int mf = 0; mf < 2; mf++)
#pragma unroll
            for (int nf = 0; nf < 4; nf++) {
                float* a = acc2[mf * 4 + nf];
                int r0 = wm * 32 + mf * 16 + g, col = wn * 32 + nf * 8 + c * 2;
                float e0 = __expf(a[0]), e1 = __expf(a[1]);
                float e2 = __expf(a[2]), e3 = __expf(a[3]);
                rs[mf * 2] += e0 + e1;
                rs[mf * 2 + 1] += e2 + e3;
                __align__(4) __nv_bfloat16 hb[2], lb[2];
                hb[0] = __float2bfloat16(e0);
                hb[1] = __float2bfloat16(e1);
                lb[0] = __float2bfloat16(e0 - __bfloat162float(hb[0]));
                lb[1] = __float2bfloat16(e1 - __bfloat162float(hb[1]));
                *(uint32_t*)(sPh + r0 * PAD + col) = *(uint32_t*)hb;
                *(uint32_t*)(sPl + r0 * PAD + col) = *(uint32_t*)lb;
                hb[0] = __float2bfloat16(e2);
                hb[1] = __float2bfloat16(e3);
                lb[0] = __float2bfloat16(e2 - __bfloat162float(hb[0]));
                lb[1] = __float2bfloat16(e3 - __bfloat162float(hb[1]));
                *(uint32_t*)(sPh + (r0 + 8) * PAD + col) = *(uint32_t*)hb;
                *(uint32_t*)(sPl + (r0 + 8) * PAD + col) = *(uint32_t*)lb;
            }
        __syncthreads();   // P visible

        // ---- AV: M=128q, N=64c, contraction k=64 ----
#pragma unroll
        for (int ks = 0; ks < 4; ks++) {
            const int k0 = ks * 16;
            uint32_t ah[2][4], al[2][4];
#pragma unroll
            for (int mf = 0; mf < 2; mf++) {
                uint32_t off = (uint32_t)((arow + mf * 16) * PAD + k0 + acol8) * 2;
                ldsm4(uPh + off, ah[mf][0], ah[mf][1], ah[mf][2], ah[mf][3]);
                ldsm4(uPl + off, al[mf][0], al[mf][1], al[mf][2], al[mf][3]);
            }
#pragma unroll
            for (int nf2 = 0; nf2 < 2; nf2++) {
                uint32_t boff = (uint32_t)((brow + nf2 * 16) * PAD + k0 + bcol8) * 2;
                uint32_t bh[4], bl[4];
                ldsm4(uVh + boff, bh[0], bh[1], bh[2], bh[3]);
                ldsm4(uVl + boff, bl[0], bl[1], bl[2], bl[3]);
#pragma unroll
                for (int mf = 0; mf < 2; mf++) {
                    float* c0 = accO[mf * 4 + nf2 * 2];
                    float* c1 = accO[mf * 4 + nf2 * 2 + 1];
                    mma16816(c0, ah[mf], bh[0], bh[1]);
                    mma16816(c0, al[mf], bh[0], bh[1]);
                    mma16816(c0, ah[mf], bl[0], bl[1]);
                    mma16816(c1, ah[mf], bh[2], bh[3]);
                    mma16816(c1, al[mf], bh[2], bh[3]);
                    mma16816(c1, ah[mf], bl[2], bl[3]);
                }
            }
        }
    }

    // ---- rowsums ----
#pragma unroll
    for (int off = 1; off <= 2; off <<= 1)
#pragma unroll
        for (int i = 0; i < 4; i++) rs[i] += __shfl_xor_sync(0xffffffffu, rs[i], off);
    __syncthreads();
    if (c == 0) {
#pragma unroll
        for (int mf = 0; mf < 2; mf++)
#pragma unroll
            for (int hh = 0; hh < 2; hh++)
                sRS[wm * 32 + mf * 16 + g + hh * 8][wn] = rs[mf * 2 + hh];
    }
    __syncthreads();
    if (wn == 0 && c == 0) {
#pragma unroll
        for (int mf = 0; mf < 2; mf++)
#pragma unroll
            for (int hh = 0; hh < 2; hh++) {
                int row = wm * 32 + mf * 16 + g + hh * 8;
                g_inv[(size_t)n * S + qb + row] = 1.f / (sRS[row][0] + sRS[row][1]);
            }
    }

    // ---- scale O, scatter into torch-faithful [B,S,DM] ----
#pragma unroll
    for (int mf = 0; mf < 2; mf++)
#pragma unroll
        for (int nf = 0; nf < 4; nf++) {
            float* a = accO[mf * 4 + nf];
            int col = wn * 32 + nf * 8 + c * 2;
#pragma unroll
            for (int hh = 0; hh < 2; hh++) {
                int row = wm * 32 + mf * 16 + g + hh * 8;
                float inv = 1.f / (sRS[row][0] + sRS[row][1]);
                int q = qb + row;
                float* dst = g_AO + ((size_t)(q >> 9) * S + ((q & 511) << 2) + (n >> 3)) * DM +
                             (n & 7) * 64 + col;
                float2 v;
                v.x = a[hh * 2] * inv;
                v.y = a[hh * 2 + 1] * inv;
                *(float2*)dst = v;
            }
        }
}

// ---------------------------------------------------------------------------
// K3: attn_w writer — recompute QK per 128x128 tile, attn = exp(s) * inv.
// ---------------------------------------------------------------------------
__global__ __launch_bounds__(256) void attn_kernel(float* __restrict__ attn)
{
    extern __shared__ char smp[];
    __nv_bfloat16* sQh = (__nv_bfloat16*)smp;       // [128][PAD]
    __nv_bfloat16* sQl = sQh + 128 * PAD;
    __nv_bfloat16* sKh = sQl + 128 * PAD;
    __nv_bfloat16* sKl = sKh + 128 * PAD;
    __shared__ float sInv[128];
    const int kb = blockIdx.x * 128, qb = blockIdx.y * 128, n = blockIdx.z;
    const int tid = threadIdx.x, wid = tid >> 5, lane = tid & 31;
    const int wm = wid >> 1, wn = wid & 1;

    const __nv_bfloat16* Qg = g_Qc + ((size_t)n * S + qb) * 128;
    const __nv_bfloat16* Kg = g_Kc + ((size_t)n * S + kb) * 128;
    for (int u = tid; u < 2048; u += 256) {
        int row = u >> 4, ch = u & 15;
        cp16(smem_u32((ch < 8 ? sQh : sQl) + row * PAD + (ch & 7) * 8), Qg + row * 128 + ch * 8);
        cp16(smem_u32((ch < 8 ? sKh : sKl) + row * PAD + (ch & 7) * 8), Kg + row * 128 + ch * 8);
    }
    CP_COMMIT();
    if (tid < 128) sInv[tid] = g_inv[(size_t)n * S + qb + tid];
    CP_WAIT0();
    __syncthreads();

    float acc[16][4];
#pragma unroll
    for (int f = 0; f < 16; f++)
#pragma unroll
        for (int e = 0; e < 4; e++) acc[f][e] = 0.f;

    const uint32_t uQh = smem_u32(sQh), uQl = smem_u32(sQl);
    const uint32_t uKh = smem_u32(sKh), uKl = smem_u32(sKl);
    const int arow = wm * 32 + (lane & 15);
    const int acol8 = (lane >> 4) << 3;
    const int brow = wn * 64 + (lane & 7) + ((lane >> 4) << 3);
    const int bcol8 = ((lane >> 3) & 1) << 3;

#pragma unroll
    for (int ks = 0; ks < 4; ks++) {
        const int k0 = ks * 16;
        uint32_t ah[2][4], al[2][4];
#pragma unroll
        for (int mf = 0; mf < 2; mf++) {
            uint32_t off = (uint32_t)((arow + mf * 16) * PAD + k0 + acol8) * 2;
            ldsm4(uQh + off, ah[mf][0], ah[mf][1], ah[mf][2], ah[mf][3]);
            ldsm4(uQl + off, al[mf][0], al[mf][1], al[mf][2], al[mf][3]);
        }
#pragma unroll
        for (int nf2 = 0; nf2 < 4; nf2++) {
            uint32_t boff = (uint32_t)((brow + nf2 * 16) * PAD + k0 + bcol8) * 2;
            uint32_t bh[4], bl[4];
            ldsm4(uKh + boff, bh[0], bh[1], bh[2], bh[3]);
            ldsm4(uKl + boff, bl[0], bl[1], bl[2], bl[3]);
#pragma unroll
            for (int mf = 0; mf < 2; mf++) {
                float* c0 = acc[mf * 8 + nf2 * 2];
                float* c1 = acc[mf * 8 + nf2 * 2 + 1];
                mma16816(c0, ah[mf], bh[0], bh[1]);
                mma16816(c0, al[mf], bh[0], bh[1]);
                mma16816(c0, ah[mf], bl[0], bl[1]);
                mma16816(c1, ah[mf], bh[2], bh[3]);
                mma16816(c1, al[mf], bh[2], bh[3]);
                mma16816(c1, ah[mf], bl[2], bl[3]);
            }
        }
    }
    __syncthreads();

    float* sS = (float*)smp;  // [128][132] staging (aliases tiles)
    const int g = lane >> 2, c = lane & 3;
#pragma unroll
    for (int mf = 0; mf < 2; mf++)
#pragma unroll
        for (int nf = 0; nf < 8; nf++) {
            float* a = acc[mf * 8 + nf];
            int r0 = wm * 32 + mf * 16 + g, col = wn * 64 + nf * 8 + c * 2;
            float i0 = sInv[r0], i1 = sInv[r0 + 8];
            sS[r0 * 132 + col] = __expf(a[0]) * i0;
            sS[r0 * 132 + col + 1] = __expf(a[1]) * i0;
            sS[(r0 + 8) * 132 + col] = __expf(a[2]) * i1;
            sS[(r0 + 8) * 132 + col + 1] = __expf(a[3]) * i1;
        }
    __syncthreads();
    for (int it = tid; it < 4096; it += 256) {
        int row = it >> 5, c4 = it & 31;
        __stcs((float4*)(attn + ((size_t)n * S + qb + row) * S + kb + c4 * 4),
               *(float4*)(sS + row * 132 + c4 * 4));
    }
}

// ---------------------------------------------------------------------------
// K4: out-projection
// ---------------------------------------------------------------------------
__global__ __launch_bounds__(256) void proj_kernel(
    const float* __restrict__ Wo, const float* __restrict__ bo, float* __restrict__ Z)
{
    const int s0 = blockIdx.x * 64, d0 = blockIdx.y * 64, bp = blockIdx.z;
    __shared__ float sW[64][33];
    __shared__ float sA[64][33];
    const int tid = threadIdx.x, tx = tid & 15, ty = tid >> 4;
    float acc[4][4] = {};
    for (int m0 = 0; m0 < DM; m0 += 32) {
#pragma unroll
        for (int r = 0; r < 2; r++) {
            int row = (tid >> 3) + r * 32, cv = (tid & 7) * 4;
            float4 w4 = *(const float4*)(Wo + (size_t)(d0 + row) * DM + m0 + cv);
            float4 a4 = *(const float4*)(g_AO + ((size_t)bp * S + s0 + row) * DM + m0 + cv);
            sW[row][cv] = w4.x; sW[row][cv + 1] = w4.y; sW[row][cv + 2] = w4.z; sW[row][cv + 3] = w4.w;
            sA[row][cv] = a4.x; sA[row][cv + 1] = a4.y; sA[row][cv + 2] = a4.z; sA[row][cv + 3] = a4.w;
        }
        __syncthreads();
#pragma unroll
        for (int kk = 0; kk < 32; kk++) {
            float a[4], c4[4];
#pragma unroll
            for (int i = 0; i < 4; i++) { a[i] = sW[ty * 4 + i][kk]; c4[i] = sA[tx * 4 + i][kk]; }
#pragma unroll
            for (int i = 0; i < 4; i++)
#pragma unroll
                for (int j = 0; j < 4; j++) acc[i][j] += a[i] * c4[j];
        }
        __syncthreads();
    }
#pragma unroll
    for (int i = 0; i < 4; i++) {
        int d = d0 + ty * 4 + i;
        float bias = bo[d];
        float4 r;
        r.x = acc[i][0] + bias; r.y = acc[i][1] + bias;
        r.z = acc[i][2] + bias; r.w = acc[i][3] + bias;
        *(float4*)(Z + (size_t)(bp * DIN + d) * S + s0 + tx * 4) = r;
    }
}

// ---------------------------------------------------------------------------
extern "C" void kernel_launch(void* const* d_in, const int* in_sizes, int n_in,
                              void* d_out, int out_size)
{
    const float* x  = (const float*)d_in[0];
    const float* Wq = (const float*)d_in[1];
    const float* bq = (const float*)d_in[2];
    const float* Wk = (const float*)d_in[3];
    const float* bk = (const float*)d_in[4];
    const float* Wv = (const float*)d_in[5];
    const float* bv = (const float*)d_in[6];
    const float* Wo = (const float*)d_in[7];
    const float* bo = (const float*)d_in[8];
    float* out = (float*)d_out;

    const long long zsz = (long long)NB * DIN * S;
    const long long asz = (long long)NB * H * S * S;
    float* attn;
    if ((long long)out_size >= zsz + asz) {
        attn = out + zsz;
    } else {
        void* p = nullptr;
        cudaGetSymbolAddress(&p, g_scratch);
        attn = (float*)p;
    }

    const int fused_smem = 1024 * PAD * 2;      // 147,456 B
    const int attn_smem  = 4 * 128 * PAD * 2;   // 73,728 B
    cudaFuncSetAttribute(fused_kernel, cudaFuncAttributeMaxDynamicSharedMemorySize, fused_smem);
    cudaFuncSetAttribute(attn_kernel, cudaFuncAttributeMaxDynamicSharedMemorySize, attn_smem);

    qkv_kernel<<<dim3(S / 64, DM / 64, NB), 256>>>(x, Wq, bq, Wk, bk, Wv, bv);
    fused_kernel<<<dim3(16, BH), 256, fused_smem>>>();
    attn_kernel<<<dim3(16, 16, BH), 256, attn_smem>>>(attn);
    proj_kernel<<<dim3(S / 64, DIN / 64, NB), 256>>>(Wo, bo, out);
}

// round 11
// speedup vs baseline: 1.1374x; 1.1374x over previous
#include <cuda_runtime.h>
#include <cuda_bf16.h>
#include <stdint.h>
#include <math.h>

#define S   2048
#define DIN 256
#define DM  512
#define NB  4
#define H   8
#define DK  64
#define BH  32
#define PAD 72

__device__ __nv_bfloat16 g_Qc[(size_t)BH * S * 128];   // [n][s][hi(64)|lo(64)]
__device__ __nv_bfloat16 g_Kc[(size_t)BH * S * 128];
__device__ __nv_bfloat16 g_Vhi[(size_t)BH * DK * S];   // [n][c][s]
__device__ __nv_bfloat16 g_Vlo[(size_t)BH * DK * S];
__device__ float g_part[(size_t)BH * S * 32];
__device__ float g_AO[(size_t)NB * S * DM];
__device__ float g_scratch[(size_t)NB * H * S * S];

__device__ __forceinline__ uint32_t smem_u32(const void* p) {
    uint32_t a;
    asm("{ .reg .u64 t; cvta.to.shared.u64 t, %1; cvt.u32.u64 %0, t; }" : "=r"(a) : "l"(p));
    return a;
}
__device__ __forceinline__ void ldsm4(uint32_t addr, uint32_t& r0, uint32_t& r1,
                                      uint32_t& r2, uint32_t& r3) {
    asm volatile("ldmatrix.sync.aligned.m8n8.x4.shared.b16 {%0,%1,%2,%3}, [%4];"
                 : "=r"(r0), "=r"(r1), "=r"(r2), "=r"(r3) : "r"(addr));
}
__device__ __forceinline__ void mma16816(float* c, const uint32_t* a, uint32_t b0, uint32_t b1) {
    asm volatile(
        "mma.sync.aligned.m16n8k16.row.col.f32.bf16.bf16.f32 "
        "{%0,%1,%2,%3},{%4,%5,%6,%7},{%8,%9},{%0,%1,%2,%3};"
        : "+f"(c[0]), "+f"(c[1]), "+f"(c[2]), "+f"(c[3])
        : "r"(a[0]), "r"(a[1]), "r"(a[2]), "r"(a[3]), "r"(b0), "r"(b1));
}
__device__ __forceinline__ void cp16(uint32_t s, const void* g) {
    asm volatile("cp.async.cg.shared.global [%0], [%1], 16;" :: "r"(s), "l"(g));
}
#define CP_COMMIT() asm volatile("cp.async.commit_group;" ::: "memory")
#define CP_WAIT0()  asm volatile("cp.async.wait_group 0;" ::: "memory")

// ---------------------------------------------------------------------------
// K1: QKV projection (fp32 SIMT) + bf16 hi/lo emission
// ---------------------------------------------------------------------------
__global__ __launch_bounds__(256) void qkv_kernel(
    const float* __restrict__ x,
    const float* __restrict__ Wq, const float* __restrict__ bq,
    const float* __restrict__ Wk, const float* __restrict__ bk,
    const float* __restrict__ Wv, const float* __restrict__ bv)
{
    const int s0 = blockIdx.x * 64, m0 = blockIdx.y * 64, b = blockIdx.z;
    __shared__ float sX[16][64];
    __shared__ float sW[3][64][16];
    const int tid = threadIdx.x, tx = tid & 15, ty = tid >> 4;
    float acc[3][4][4];
#pragma unroll
    for (int w = 0; w < 3; w++)
#pragma unroll
        for (int i = 0; i < 4; i++)
#pragma unroll
            for (int j = 0; j < 4; j++) acc[w][i][j] = 0.f;

    for (int d0 = 0; d0 < DIN; d0 += 16) {
        {
            int dd = tid >> 4, sv = (tid & 15) * 4;
            *(float4*)&sX[dd][sv] = *(const float4*)(x + (size_t)(b * DIN + d0 + dd) * S + s0 + sv);
        }
        {
            int mm = tid >> 2, dv = (tid & 3) * 4;
            const int wofs = (m0 + mm) * DIN + d0 + dv;
            *(float4*)&sW[0][mm][dv] = *(const float4*)(Wq + wofs);
            *(float4*)&sW[1][mm][dv] = *(const float4*)(Wk + wofs);
            *(float4*)&sW[2][mm][dv] = *(const float4*)(Wv + wofs);
        }
        __syncthreads();
#pragma unroll
        for (int dd = 0; dd < 16; dd++) {
            float xb[4];
            *(float4*)xb = *(float4*)&sX[dd][tx * 4];
#pragma unroll
            for (int w = 0; w < 3; w++) {
                float wr[4];
#pragma unroll
                for (int i = 0; i < 4; i++) wr[i] = sW[w][ty * 4 + i][dd];
#pragma unroll
                for (int i = 0; i < 4; i++)
#pragma unroll
                    for (int j = 0; j < 4; j++) acc[w][i][j] += wr[i] * xb[j];
            }
        }
        __syncthreads();
    }

    const int n = b * 8 + (m0 >> 6);
    const float* bs[3] = {bq, bk, bv};
#pragma unroll
    for (int w = 0; w < 3; w++) {
        float v[4][4];
#pragma unroll
        for (int i = 0; i < 4; i++) {
            float bb = bs[w][m0 + ty * 4 + i];
#pragma unroll
            for (int j = 0; j < 4; j++) v[i][j] = acc[w][i][j] + bb;
        }
        if (w < 2) {
            __nv_bfloat16* dst = (w == 0) ? g_Qc : g_Kc;
#pragma unroll
            for (int j = 0; j < 4; j++) {
                __align__(8) __nv_bfloat16 hi[4], lo[4];
#pragma unroll
                for (int i = 0; i < 4; i++) {
                    float p = v[i][j];
                    hi[i] = __float2bfloat16(p);
                    lo[i] = __float2bfloat16(p - __bfloat162float(hi[i]));
                }
                size_t off = ((size_t)n * S + s0 + tx * 4 + j) * 128 + ty * 4;
                *(uint2*)(dst + off) = *(uint2*)hi;
                *(uint2*)(dst + off + 64) = *(uint2*)lo;
            }
        } else {
#pragma unroll
            for (int i = 0; i < 4; i++) {
                __align__(8) __nv_bfloat16 hi[4], lo[4];
#pragma unroll
                for (int j = 0; j < 4; j++) {
                    float p = v[i][j];
                    hi[j] = __float2bfloat16(p);
                    lo[j] = __float2bfloat16(p - __bfloat162float(hi[j]));
                }
                size_t off = ((size_t)n * DK + ty * 4 + i) * S + s0 + tx * 4;
                *(uint2*)(g_Vhi + off) = *(uint2*)hi;
                *(uint2*)(g_Vlo + off) = *(uint2*)lo;
            }
        }
    }
}

// ---------------------------------------------------------------------------
// K2: scores via mma.sync hi/lo (3 products). Writes exp(S) + partial rowsums.
// ---------------------------------------------------------------------------
__global__ __launch_bounds__(256) void score_kernel(float* __restrict__ attn)
{
    extern __shared__ char smp[];
    __nv_bfloat16* sQh = (__nv_bfloat16*)smp;       // [128][PAD]
    __nv_bfloat16* sQl = sQh + 128 * PAD;
    __nv_bfloat16* sKh = sQl + 128 * PAD;
    __nv_bfloat16* sKl = sKh + 128 * PAD;
    const int kb = blockIdx.x * 128, qb = blockIdx.y * 128, n = blockIdx.z;
    const int tid = threadIdx.x, wid = tid >> 5, lane = tid & 31;
    const int wm = wid >> 1, wn = wid & 1;

    const __nv_bfloat16* Qg = g_Qc + ((size_t)n * S + qb) * 128;
    const __nv_bfloat16* Kg = g_Kc + ((size_t)n * S + kb) * 128;
    for (int u = tid; u < 2048; u += 256) {
        int row = u >> 4, ch = u & 15;
        __nv_bfloat16* dq = (ch < 8 ? sQh : sQl) + row * PAD + (ch & 7) * 8;
        __nv_bfloat16* dk = (ch < 8 ? sKh : sKl) + row * PAD + (ch & 7) * 8;
        cp16(smem_u32(dq), Qg + row * 128 + ch * 8);
        cp16(smem_u32(dk), Kg + row * 128 + ch * 8);
    }
    CP_COMMIT();
    CP_WAIT0();
    __syncthreads();

    float acc[16][4];
#pragma unroll
    for (int f = 0; f < 16; f++)
#pragma unroll
        for (int e = 0; e < 4; e++) acc[f][e] = 0.f;

    const uint32_t uQh = smem_u32(sQh), uQl = smem_u32(sQl);
    const uint32_t uKh = smem_u32(sKh), uKl = smem_u32(sKl);
    const int arow = wm * 32 + (lane & 15);
    const int acol8 = (lane >> 4) << 3;
    const int brow = wn * 64 + (lane & 7) + ((lane >> 4) << 3);
    const int bcol8 = ((lane >> 3) & 1) << 3;

#pragma unroll
    for (int ks = 0; ks < 4; ks++) {
        const int k0 = ks * 16;
        uint32_t ah[2][4], al[2][4];
#pragma unroll
        for (int mf = 0; mf < 2; mf++) {
            uint32_t off = (uint32_t)((arow + mf * 16) * PAD + k0 + acol8) * 2;
            ldsm4(uQh + off, ah[mf][0], ah[mf][1], ah[mf][2], ah[mf][3]);
            ldsm4(uQl + off, al[mf][0], al[mf][1], al[mf][2], al[mf][3]);
        }
#pragma unroll
        for (int nf2 = 0; nf2 < 4; nf2++) {
            uint32_t boff = (uint32_t)((brow + nf2 * 16) * PAD + k0 + bcol8) * 2;
            uint32_t bh[4], bl[4];
            ldsm4(uKh + boff, bh[0], bh[1], bh[2], bh[3]);
            ldsm4(uKl + boff, bl[0], bl[1], bl[2], bl[3]);
#pragma unroll
            for (int mf = 0; mf < 2; mf++) {
                float* c0 = acc[mf * 8 + nf2 * 2];
                float* c1 = acc[mf * 8 + nf2 * 2 + 1];
                mma16816(c0, ah[mf], bh[0], bh[1]);
                mma16816(c0, al[mf], bh[0], bh[1]);
                mma16816(c0, ah[mf], bl[0], bl[1]);
                mma16816(c1, ah[mf], bh[2], bh[3]);
                mma16816(c1, al[mf], bh[2], bh[3]);
                mma16816(c1, ah[mf], bl[2], bl[3]);
            }
        }
    }
    __syncthreads();

    float* sS = (float*)smp;  // [128][132]
    const int g = lane >> 2, c = lane & 3;
    float rsum[4] = {0.f, 0.f, 0.f, 0.f};
#pragma unroll
    for (int mf = 0; mf < 2; mf++)
#pragma unroll
        for (int nf = 0; nf < 8; nf++) {
            float* a = acc[mf * 8 + nf];
            int r0 = wm * 32 + mf * 16 + g, col = wn * 64 + nf * 8 + c * 2;
            float e0 = __expf(a[0]), e1 = __expf(a[1]);
            float e2 = __expf(a[2]), e3 = __expf(a[3]);
            sS[r0 * 132 + col] = e0;       sS[r0 * 132 + col + 1] = e1;
            sS[(r0 + 8) * 132 + col] = e2; sS[(r0 + 8) * 132 + col + 1] = e3;
            rsum[mf * 2] += e0 + e1;
            rsum[mf * 2 + 1] += e2 + e3;
        }
#pragma unroll
    for (int off = 1; off <= 2; off <<= 1)
#pragma unroll
        for (int i = 0; i < 4; i++) rsum[i] += __shfl_xor_sync(0xffffffffu, rsum[i], off);
    if (c == 0) {
#pragma unroll
        for (int mf = 0; mf < 2; mf++)
#pragma unroll
            for (int hh = 0; hh < 2; hh++) {
                int r = wm * 32 + mf * 16 + g + hh * 8;
                g_part[((size_t)n * S + qb + r) * 32 + blockIdx.x * 2 + wn] = rsum[mf * 2 + hh];
            }
    }
    __syncthreads();
    for (int it = tid; it < 4096; it += 256) {
        int row = it >> 5, c4 = it & 31;
        __stcs((float4*)(attn + ((size_t)n * S + qb + row) * S + kb + c4 * 4),
               *(float4*)(sS + row * 132 + c4 * 4));
    }
}

// ---------------------------------------------------------------------------
// K3 helper: normalize E regs -> streaming attn_w store + hi/lo SMEM tiles
// ---------------------------------------------------------------------------
__device__ __forceinline__ void conv_chunk(
    const float4* e, float* attnC, int r0, int u, const float* sInv,
    __nv_bfloat16* Ph, __nv_bfloat16* Pl)
{
#pragma unroll
    for (int i = 0; i < 8; i++) {
        int row = r0 + i * 16;
        float iv = sInv[row];
        float4 v = e[i];
        v.x *= iv; v.y *= iv; v.z *= iv; v.w *= iv;
        __stcs((float4*)(attnC + (size_t)row * S + u * 4), v);
        float ef[4] = {v.x, v.y, v.z, v.w};
        __align__(8) __nv_bfloat16 hb[4], lb[4];
#pragma unroll
        for (int j = 0; j < 4; j++) {
            hb[j] = __float2bfloat16(ef[j]);
            lb[j] = __float2bfloat16(ef[j] - __bfloat162float(hb[j]));
        }
        *(uint2*)(Ph + row * PAD + u * 4) = *(uint2*)hb;
        *(uint2*)(Pl + row * PAD + u * 4) = *(uint2*)lb;
    }
}

// ---------------------------------------------------------------------------
// K3: pipelined AV (reduce folded into prologue): prefetch E/V(kc+1) ->
// MMA(kc) -> convert -> 1 sync.
// ---------------------------------------------------------------------------
__global__ __launch_bounds__(256) void av_kernel(float* __restrict__ attn)
{
    extern __shared__ char smp[];
    __nv_bfloat16* sPh = (__nv_bfloat16*)smp;         // [2][128*PAD]
    __nv_bfloat16* sPl = sPh + 2 * 128 * PAD;
    __nv_bfloat16* sVh = sPl + 2 * 128 * PAD;         // [2][64*PAD]
    __nv_bfloat16* sVl = sVh + 2 * 64 * PAD;
    __shared__ float sInv[128];
    const int qb = blockIdx.x * 128, n = blockIdx.y;
    const int tid = threadIdx.x, wid = tid >> 5, lane = tid & 31;
    const int wm = wid >> 1, wn = wid & 1;
    const int r0 = tid >> 4, u = tid & 15;

    // folded reduce: sum the 32 partials for this row (index order == old
    // reduce_kernel order -> bitwise identical inv)
    if (tid < 128) {
        const float* p = g_part + ((size_t)n * S + qb + tid) * 32;
        float s = 0.f;
#pragma unroll
        for (int i8 = 0; i8 < 8; i8++) {
            float4 v4 = *(const float4*)(p + i8 * 4);
            s = ((((((s + v4.x) + v4.y) + v4.z) + v4.w)));
        }
        sInv[tid] = 1.f / s;
    }
    __syncthreads();

    float* attnBase = attn + ((size_t)n * S + qb) * S;
    const __nv_bfloat16* Vh = g_Vhi + (size_t)n * DK * S;
    const __nv_bfloat16* Vl = g_Vlo + (size_t)n * DK * S;

    // prologue: chunk 0
    float4 e[8];
#pragma unroll
    for (int i = 0; i < 8; i++)
        e[i] = __ldcs((const float4*)(attnBase + (size_t)(r0 + i * 16) * S + u * 4));
#pragma unroll
    for (int j = 0; j < 2; j++) {
        int idx = tid + j * 256, cc = idx >> 3, uu = idx & 7;
        size_t go = (size_t)cc * S + uu * 8;
        cp16(smem_u32(sVh + cc * PAD + uu * 8), Vh + go);
        cp16(smem_u32(sVl + cc * PAD + uu * 8), Vl + go);
    }
    CP_COMMIT();
    conv_chunk(e, attnBase, r0, u, sInv, sPh, sPl);
    CP_WAIT0();
    __syncthreads();

    float acc[8][4];
#pragma unroll
    for (int f = 0; f < 8; f++)
#pragma unroll
        for (int ee = 0; ee < 4; ee++) acc[f][ee] = 0.f;

    const int arow = wm * 32 + (lane & 15);
    const int acol8 = (lane >> 4) << 3;
    const int brow = wn * 32 + (lane & 7) + ((lane >> 4) << 3);
    const int bcol8 = ((lane >> 3) & 1) << 3;

    for (int kc = 0; kc < 32; kc++) {
        const int buf = kc & 1, nxt = buf ^ 1;
        if (kc < 31) {
            float* aC = attnBase + (kc + 1) * 64;
#pragma unroll
            for (int i = 0; i < 8; i++)
                e[i] = __ldcs((const float4*)(aC + (size_t)(r0 + i * 16) * S + u * 4));
#pragma unroll
            for (int j = 0; j < 2; j++) {
                int idx = tid + j * 256, cc = idx >> 3, uu = idx & 7;
                size_t go = (size_t)cc * S + (kc + 1) * 64 + uu * 8;
                cp16(smem_u32(sVh + nxt * 64 * PAD + cc * PAD + uu * 8), Vh + go);
                cp16(smem_u32(sVl + nxt * 64 * PAD + cc * PAD + uu * 8), Vl + go);
            }
            CP_COMMIT();
        }
        // MMA on buffer `buf`
        const uint32_t uPh = smem_u32(sPh + buf * 128 * PAD);
        const uint32_t uPl = smem_u32(sPl + buf * 128 * PAD);
        const uint32_t uVh = smem_u32(sVh + buf * 64 * PAD);
        const uint32_t uVl = smem_u32(sVl + buf * 64 * PAD);
#pragma unroll
        for (int ks = 0; ks < 4; ks++) {
            const int k0 = ks * 16;
            uint32_t ah[2][4], al[2][4];
#pragma unroll
            for (int mf = 0; mf < 2; mf++) {
                uint32_t off = (uint32_t)((arow + mf * 16) * PAD + k0 + acol8) * 2;
                ldsm4(uPh + off, ah[mf][0], ah[mf][1], ah[mf][2], ah[mf][3]);
                ldsm4(uPl + off, al[mf][0], al[mf][1], al[mf][2], al[mf][3]);
            }
#pragma unroll
            for (int nf2 = 0; nf2 < 2; nf2++) {
                uint32_t boff = (uint32_t)((brow + nf2 * 16) * PAD + k0 + bcol8) * 2;
                uint32_t bh[4], bl[4];
                ldsm4(uVh + boff, bh[0], bh[1], bh[2], bh[3]);
                ldsm4(uVl + boff, bl[0], bl[1], bl[2], bl[3]);
#pragma unroll
                for (int mf = 0; mf < 2; mf++) {
                    float* c0 = acc[mf * 4 + nf2 * 2];
                    float* c1 = acc[mf * 4 + nf2 * 2 + 1];
                    mma16816(c0, ah[mf], bh[0], bh[1]);
                    mma16816(c0, al[mf], bh[0], bh[1]);
                    mma16816(c0, ah[mf], bl[0], bl[1]);
                    mma16816(c1, ah[mf], bh[2], bh[3]);
                    mma16816(c1, al[mf], bh[2], bh[3]);
                    mma16816(c1, ah[mf], bl[2], bl[3]);
                }
            }
        }
        if (kc < 31) {
            conv_chunk(e, attnBase + (kc + 1) * 64, r0, u, sInv,
                       sPh + nxt * 128 * PAD, sPl + nxt * 128 * PAD);
            CP_WAIT0();
        }
        __syncthreads();
    }

    // scatter O into torch-faithful [B,S,DM]
    const int g = lane >> 2, c = lane & 3;
#pragma unroll
    for (int mf = 0; mf < 2; mf++)
#pragma unroll
        for (int nf = 0; nf < 4; nf++) {
            float* a = acc[mf * 4 + nf];
            int col = wn * 32 + nf * 8 + c * 2;
#pragma unroll
            for (int hh = 0; hh < 2; hh++) {
                int q = qb + wm * 32 + mf * 16 + g + hh * 8;
                float* dst = g_AO + ((size_t)(q >> 9) * S + ((q & 511) << 2) + (n >> 3)) * DM +
                             (n & 7) * 64 + col;
                float2 v;
                v.x = a[hh * 2]; v.y = a[hh * 2 + 1];
                *(float2*)dst = v;
            }
        }
}

// ---------------------------------------------------------------------------
// K4: out-projection
// ---------------------------------------------------------------------------
__global__ __launch_bounds__(256) void proj_kernel(
    const float* __restrict__ Wo, const float* __restrict__ bo, float* __restrict__ Z)
{
    const int s0 = blockIdx.x * 64, d0 = blockIdx.y * 64, bp = blockIdx.z;
    __shared__ float sW[64][33];
    __shared__ float sA[64][33];
    const int tid = threadIdx.x, tx = tid & 15, ty = tid >> 4;
    float acc[4][4] = {};
    for (int m0 = 0; m0 < DM; m0 += 32) {
#pragma unroll
        for (int r = 0; r < 2; r++) {
            int row = (tid >> 3) + r * 32, cv = (tid & 7) * 4;
            float4 w4 = *(const float4*)(Wo + (size_t)(d0 + row) * DM + m0 + cv);
            float4 a4 = *(const float4*)(g_AO + ((size_t)bp * S + s0 + row) * DM + m0 + cv);
            sW[row][cv] = w4.x; sW[row][cv + 1] = w4.y; sW[row][cv + 2] = w4.z; sW[row][cv + 3] = w4.w;
            sA[row][cv] = a4.x; sA[row][cv + 1] = a4.y; sA[row][cv + 2] = a4.z; sA[row][cv + 3] = a4.w;
        }
        __syncthreads();
#pragma unroll
        for (int kk = 0; kk < 32; kk++) {
            float a[4], c4[4];
#pragma unroll
            for (int i = 0; i < 4; i++) { a[i] = sW[ty * 4 + i][kk]; c4[i] = sA[tx * 4 + i][kk]; }
#pragma unroll
            for (int i = 0; i < 4; i++)
#pragma unroll
                for (int j = 0; j < 4; j++) acc[i][j] += a[i] * c4[j];
        }
        __syncthreads();
    }
#pragma unroll
    for (int i = 0; i < 4; i++) {
        int d = d0 + ty * 4 + i;
        float bias = bo[d];
        float4 r;
        r.x = acc[i][0] + bias; r.y = acc[i][1] + bias;
        r.z = acc[i][2] + bias; r.w = acc[i][3] + bias;
        *(float4*)(Z + (size_t)(bp * DIN + d) * S + s0 + tx * 4) = r;
    }
}

// ---------------------------------------------------------------------------
extern "C" void kernel_launch(void* const* d_in, const int* in_sizes, int n_in,
                              void* d_out, int out_size)
{
    const float* x  = (const float*)d_in[0];
    const float* Wq = (const float*)d_in[1];
    const float* bq = (const float*)d_in[2];
    const float* Wk = (const float*)d_in[3];
    const float* bk = (const float*)d_in[4];
    const float* Wv = (const float*)d_in[5];
    const float* bv = (const float*)d_in[6];
    const float* Wo = (const float*)d_in[7];
    const float* bo = (const float*)d_in[8];
    float* out = (float*)d_out;

    const long long zsz = (long long)NB * DIN * S;
    const long long asz = (long long)NB * H * S * S;
    float* attn;
    if ((long long)out_size >= zsz + asz) {
        attn = out + zsz;
    } else {
        void* p = nullptr;
        cudaGetSymbolAddress(&p, g_scratch);
        attn = (float*)p;
    }

    const int score_smem = 4 * 128 * PAD * 2;            // 73,728 B
    const int av_smem    = 2 * (2 * 128 + 2 * 64) * PAD * 2; // 110,592 B
    cudaFuncSetAttribute(score_kernel, cudaFuncAttributeMaxDynamicSharedMemorySize, score_smem);
    cudaFuncSetAttribute(av_kernel, cudaFuncAttributeMaxDynamicSharedMemorySize, av_smem);

    qkv_kernel<<<dim3(S / 64, DM / 64, NB), 256>>>(x, Wq, bq, Wk, bk, Wv, bv);
    score_kernel<<<dim3(16, 16, BH), 256, score_smem>>>(attn);
    av_kernel<<<dim3(16, BH), 256, av_smem>>>(attn);
    proj_kernel<<<dim3(S / 64, DIN / 64, NB), 256>>>(Wo, bo, out);
}

// round 13
// speedup vs baseline: 1.3993x; 1.2303x over previous
#include <cuda_runtime.h>
#include <cuda_bf16.h>
#include <stdint.h>
#include <math.h>

#define S   2048
#define DIN 256
#define DM  512
#define NB  4
#define H   8
#define DK  64
#define BH  32
#define PAD 72

__device__ __nv_bfloat16 g_Qc[(size_t)BH * S * 128];   // [n][s][hi(64)|lo(64)]
__device__ __nv_bfloat16 g_Kc[(size_t)BH * S * 128];
__device__ __nv_bfloat16 g_Vhi[(size_t)BH * DK * S];   // [n][c][s]
__device__ __nv_bfloat16 g_Vlo[(size_t)BH * DK * S];
__device__ float g_part[(size_t)BH * S * 32];
__device__ __nv_bfloat16 g_AOh[(size_t)NB * S * DM];   // attn_out hi/lo [B][S][DM]
__device__ __nv_bfloat16 g_AOl[(size_t)NB * S * DM];
__device__ __nv_bfloat16 g_xth[(size_t)NB * S * DIN];  // x^T hi/lo [b][s][d]
__device__ __nv_bfloat16 g_xtl[(size_t)NB * S * DIN];
__device__ __nv_bfloat16 g_Wh[524288];                 // Wq|Wk|Wv|Wo hi
__device__ __nv_bfloat16 g_Wl[524288];                 // lo
__device__ float g_scratch[(size_t)NB * H * S * S];

__device__ __forceinline__ uint32_t smem_u32(const void* p) {
    uint32_t a;
    asm("{ .reg .u64 t; cvta.to.shared.u64 t, %1; cvt.u32.u64 %0, t; }" : "=r"(a) : "l"(p));
    return a;
}
__device__ __forceinline__ void ldsm4(uint32_t addr, uint32_t& r0, uint32_t& r1,
                                      uint32_t& r2, uint32_t& r3) {
    asm volatile("ldmatrix.sync.aligned.m8n8.x4.shared.b16 {%0,%1,%2,%3}, [%4];"
                 : "=r"(r0), "=r"(r1), "=r"(r2), "=r"(r3) : "r"(addr));
}
__device__ __forceinline__ void mma16816(float* c, const uint32_t* a, uint32_t b0, uint32_t b1) {
    asm volatile(
        "mma.sync.aligned.m16n8k16.row.col.f32.bf16.bf16.f32 "
        "{%0,%1,%2,%3},{%4,%5,%6,%7},{%8,%9},{%0,%1,%2,%3};"
        : "+f"(c[0]), "+f"(c[1]), "+f"(c[2]), "+f"(c[3])
        : "r"(a[0]), "r"(a[1]), "r"(a[2]), "r"(a[3]), "r"(b0), "r"(b1));
}
__device__ __forceinline__ void cp16(uint32_t s, const void* g) {
    asm volatile("cp.async.cg.shared.global [%0], [%1], 16;" :: "r"(s), "l"(g));
}
#define CP_COMMIT() asm volatile("cp.async.commit_group;" ::: "memory")
#define CP_WAIT0()  asm volatile("cp.async.wait_group 0;" ::: "memory")

__device__ __forceinline__ uint32_t hilo_hi(float a, float b, __nv_bfloat16* hs) {
    hs[0] = __float2bfloat16(a);
    hs[1] = __float2bfloat16(b);
    uint32_t r;
    memcpy(&r, hs, 4);
    return r;
}

// ---------------------------------------------------------------------------
// P0a: x [b][d][s] fp32 -> xt hi/lo [b][s][d] bf16 (32x32 smem transpose)
// ---------------------------------------------------------------------------
__global__ __launch_bounds__(256) void xconv_kernel(const float* __restrict__ x)
{
    __shared__ float sT[32][33];
    const int s0 = blockIdx.x * 32, d0 = blockIdx.y * 32, b = blockIdx.z;
    const int c = threadIdx.x & 31, r4 = threadIdx.x >> 5;
#pragma unroll
    for (int i = 0; i < 4; i++) {
        int r = r4 * 4 + i;
        sT[r][c] = x[(size_t)(b * DIN + d0 + r) * S + s0 + c];
    }
    __syncthreads();
    const int sl = threadIdx.x >> 3, dg = (threadIdx.x & 7) * 4;
    __align__(8) __nv_bfloat16 hi[4], lo[4];
#pragma unroll
    for (int j = 0; j < 4; j++) {
        float v = sT[dg + j][sl];
        hi[j] = __float2bfloat16(v);
        lo[j] = __float2bfloat16(v - __bfloat162float(hi[j]));
    }
    size_t off = ((size_t)b * S + s0 + sl) * DIN + d0 + dg;
    *(uint2*)(g_xth + off) = *(uint2*)hi;
    *(uint2*)(g_xtl + off) = *(uint2*)lo;
}

// ---------------------------------------------------------------------------
// P0b: Wq|Wk|Wv|Wo -> hi/lo (each 131072 elems, packed at region*131072)
// ---------------------------------------------------------------------------
__global__ __launch_bounds__(256) void wconv_kernel(
    const float* __restrict__ Wq, const float* __restrict__ Wk,
    const float* __restrict__ Wv, const float* __restrict__ Wo)
{
    int idx = blockIdx.x * 256 + threadIdx.x;   // 0..131071
    int base = idx * 4;
    const float* srcs[4] = {Wq, Wk, Wv, Wo};
    float4 v = *(const float4*)(srcs[base >> 17] + (base & 131071));
    float vf[4] = {v.x, v.y, v.z, v.w};
    __align__(8) __nv_bfloat16 hi[4], lo[4];
#pragma unroll
    for (int j = 0; j < 4; j++) {
        hi[j] = __float2bfloat16(vf[j]);
        lo[j] = __float2bfloat16(vf[j] - __bfloat162float(hi[j]));
    }
    *(uint2*)(g_Wh + base) = *(uint2*)hi;
    *(uint2*)(g_Wl + base) = *(uint2*)lo;
}

// ---------------------------------------------------------------------------
// K1: QKV via mma hi/lo. CTA: 64m (one head) x 64s; 8 warps (4 wm x 2 wn);
// warp 16m x 32s. d=256 in 4 chunks. SMEM: X(128 rows) + W(384 rows) = 512*PAD.
// ---------------------------------------------------------------------------
__global__ __launch_bounds__(256) void qkv_mma_kernel(
    const float* __restrict__ bq, const float* __restrict__ bk,
    const float* __restrict__ bv)
{
    extern __shared__ __nv_bfloat16 smq[];
    __nv_bfloat16* sXh = smq;                 // [64][PAD]
    __nv_bfloat16* sXl = smq + 64 * PAD;
    __nv_bfloat16* sWh = smq + 128 * PAD;     // [3][64][PAD]
    __nv_bfloat16* sWl = smq + 320 * PAD;     // [3][64][PAD]  (total 512*PAD)
    const int s0 = blockIdx.x * 64, h = blockIdx.y, b = blockIdx.z;
    const int n = b * 8 + h, m0 = h * 64;
    const int tid = threadIdx.x, wid = tid >> 5, lane = tid & 31;
    const int wm = wid >> 1, wn = wid & 1;
    const uint32_t uXh = smem_u32(sXh), uXl = smem_u32(sXl);
    const uint32_t uWh = smem_u32(sWh), uWl = smem_u32(sWl);
    const int arow = wm * 16 + (lane & 15);
    const int acol8 = (lane >> 4) << 3;
    const int brow = wn * 32 + (lane & 7) + ((lane >> 4) << 3);
    const int bcol8 = ((lane >> 3) & 1) << 3;

    float acc[3][4][4];
#pragma unroll
    for (int w = 0; w < 3; w++)
#pragma unroll
        for (int f = 0; f < 4; f++)
#pragma unroll
            for (int e = 0; e < 4; e++) acc[w][f][e] = 0.f;

    for (int dc = 0; dc < 4; dc++) {
        const int d0 = dc * 64;
        for (int u = tid; u < 1024; u += 256) {
            int half = u >> 9, r = (u >> 3) & 63, ch = u & 7;
            cp16(smem_u32((half ? sXl : sXh) + r * PAD + ch * 8),
                 (half ? g_xtl : g_xth) + ((size_t)b * S + s0 + r) * DIN + d0 + ch * 8);
        }
        for (int u = tid; u < 3072; u += 256) {
            int w = u >> 10, rest = u & 1023;
            int half = rest >> 9, r = (rest >> 3) & 63, ch = rest & 7;
            cp16(smem_u32((half ? sWl : sWh) + w * 64 * PAD + r * PAD + ch * 8),
                 (half ? g_Wl : g_Wh) + w * 131072 + (size_t)(m0 + r) * DIN + d0 + ch * 8);
        }
        CP_COMMIT();
        CP_WAIT0();
        __syncthreads();
#pragma unroll
        for (int ks = 0; ks < 4; ks++) {
            const int k0 = ks * 16;
            uint32_t bh[2][4], bl[2][4];
#pragma unroll
            for (int nf2 = 0; nf2 < 2; nf2++) {
                uint32_t boff = (uint32_t)((brow + nf2 * 16) * PAD + k0 + bcol8) * 2;
                ldsm4(uXh + boff, bh[nf2][0], bh[nf2][1], bh[nf2][2], bh[nf2][3]);
                ldsm4(uXl + boff, bl[nf2][0], bl[nf2][1], bl[nf2][2], bl[nf2][3]);
            }
#pragma unroll
            for (int w = 0; w < 3; w++) {
                uint32_t aoff = (uint32_t)(w * 64 * PAD + arow * PAD + k0 + acol8) * 2;
                uint32_t ah[4], al[4];
                ldsm4(uWh + aoff, ah[0], ah[1], ah[2], ah[3]);
                ldsm4(uWl + aoff, al[0], al[1], al[2], al[3]);
#pragma unroll
                for (int nf2 = 0; nf2 < 2; nf2++) {
                    float* c0 = acc[w][nf2 * 2];
                    float* c1 = acc[w][nf2 * 2 + 1];
                    mma16816(c0, ah, bh[nf2][0], bh[nf2][1]);
                    mma16816(c0, al, bh[nf2][0], bh[nf2][1]);
                    mma16816(c0, ah, bl[nf2][0], bl[nf2][1]);
                    mma16816(c1, ah, bh[nf2][2], bh[nf2][3]);
                    mma16816(c1, al, bh[nf2][2], bh[nf2][3]);
                    mma16816(c1, ah, bl[nf2][2], bl[nf2][3]);
                }
            }
        }
        __syncthreads();
    }

    const int g = lane >> 2, cq = lane & 3;
    // ---- V (w=2): direct stores into [n][c][s] ----
#pragma unroll
    for (int nf = 0; nf < 4; nf++)
#pragma unroll
        for (int rr = 0; rr < 2; rr++) {
            int row = wm * 16 + g + rr * 8;
            float bb = __ldg(bv + m0 + row);
            int col = wn * 32 + nf * 8 + cq * 2;
            float v0 = acc[2][nf][rr * 2] + bb, v1 = acc[2][nf][rr * 2 + 1] + bb;
            __align__(4) __nv_bfloat16 hb[2], lb[2];
            uint32_t hp = hilo_hi(v0, v1, hb);
            lb[0] = __float2bfloat16(v0 - __bfloat162float(hb[0]));
            lb[1] = __float2bfloat16(v1 - __bfloat162float(hb[1]));
            uint32_t lp;
            memcpy(&lp, lb, 4);
            size_t off = ((size_t)n * DK + row) * S + s0 + col;
            *(uint32_t*)(g_Vhi + off) = hp;
            *(uint32_t*)(g_Vlo + off) = lp;
        }

    // ---- Q (w=0), K (w=1): stage [64s][136] then coalesced 256B-row copy ----
    __nv_bfloat16* sStage = smq;  // aliases X region (8704 elems <= 9216)
    const float* bsrc[2] = {bq, bk};
    __nv_bfloat16* dsts[2] = {g_Qc, g_Kc};
#pragma unroll
    for (int w = 0; w < 2; w++) {
#pragma unroll
        for (int nf = 0; nf < 4; nf++)
#pragma unroll
            for (int rr = 0; rr < 2; rr++) {
                int row = wm * 16 + g + rr * 8;
                float bb = __ldg(bsrc[w] + m0 + row);
                int col = wn * 32 + nf * 8 + cq * 2;
                float v0 = acc[w][nf][rr * 2] + bb, v1 = acc[w][nf][rr * 2 + 1] + bb;
                __nv_bfloat16 h0 = __float2bfloat16(v0);
                __nv_bfloat16 h1 = __float2bfloat16(v1);
                sStage[(col + 0) * 136 + row] = h0;
                sStage[(col + 0) * 136 + 64 + row] =
                    __float2bfloat16(v0 - __bfloat162float(h0));
                sStage[(col + 1) * 136 + row] = h1;
                sStage[(col + 1) * 136 + 64 + row] =
                    __float2bfloat16(v1 - __bfloat162float(h1));
            }
        __syncthreads();
        __nv_bfloat16* dst = dsts[w] + ((size_t)n * S + s0) * 128;
        for (int u = tid; u < 1024; u += 256) {
            int r = u >> 4, ch = u & 15;
            *(uint4*)(dst + r * 128 + ch * 8) = *(uint4*)&sStage[r * 136 + ch * 8];
        }
        __syncthreads();
    }
}

// ---------------------------------------------------------------------------
// K2: scores via mma.sync hi/lo (3 products). Writes exp(S) + partial rowsums.
// ---------------------------------------------------------------------------
__global__ __launch_bounds__(256) void score_kernel(float* __restrict__ attn)
{
    extern __shared__ char smp[];
    __nv_bfloat16* sQh = (__nv_bfloat16*)smp;       // [128][PAD]
    __nv_bfloat16* sQl = sQh + 128 * PAD;
    __nv_bfloat16* sKh = sQl + 128 * PAD;
    __nv_bfloat16* sKl = sKh + 128 * PAD;
    const int kb = blockIdx.x * 128, qb = blockIdx.y * 128, n = blockIdx.z;
    const int tid = threadIdx.x, wid = tid >> 5, lane = tid & 31;
    const int wm = wid >> 1, wn = wid & 1;

    const __nv_bfloat16* Qg = g_Qc + ((size_t)n * S + qb) * 128;
    const __nv_bfloat16* Kg = g_Kc + ((size_t)n * S + kb) * 128;
    for (int u = tid; u < 2048; u += 256) {
        int row = u >> 4, ch = u & 15;
        __nv_bfloat16* dq = (ch < 8 ? sQh : sQl) + row * PAD + (ch & 7) * 8;
        __nv_bfloat16* dk = (ch < 8 ? sKh : sKl) + row * PAD + (ch & 7) * 8;
        cp16(smem_u32(dq), Qg + row * 128 + ch * 8);
        cp16(smem_u32(dk), Kg + row * 128 + ch * 8);
    }
    CP_COMMIT();
    CP_WAIT0();
    __syncthreads();

    float acc[16][4];
#pragma unroll
    for (int f = 0; f < 16; f++)
#pragma unroll
        for (int e = 0; e < 4; e++) acc[f][e] = 0.f;

    const uint32_t uQh = smem_u32(sQh), uQl = smem_u32(sQl);
    const uint32_t uKh = smem_u32(sKh), uKl = smem_u32(sKl);
    const int arow = wm * 32 + (lane & 15);
    const int acol8 = (lane >> 4) << 3;
    const int brow = wn * 64 + (lane & 7) + ((lane >> 4) << 3);
    const int bcol8 = ((lane >> 3) & 1) << 3;

#pragma unroll
    for (int ks = 0; ks < 4; ks++) {
        const int k0 = ks * 16;
        uint32_t ah[2][4], al[2][4];
#pragma unroll
        for (int mf = 0; mf < 2; mf++) {
            uint32_t off = (uint32_t)((arow + mf * 16) * PAD + k0 + acol8) * 2;
            ldsm4(uQh + off, ah[mf][0], ah[mf][1], ah[mf][2], ah[mf][3]);
            ldsm4(uQl + off, al[mf][0], al[mf][1], al[mf][2], al[mf][3]);
        }
#pragma unroll
        for (int nf2 = 0; nf2 < 4; nf2++) {
            uint32_t boff = (uint32_t)((brow + nf2 * 16) * PAD + k0 + bcol8) * 2;
            uint32_t bh[4], bl[4];
            ldsm4(uKh + boff, bh[0], bh[1], bh[2], bh[3]);
            ldsm4(uKl + boff, bl[0], bl[1], bl[2], bl[3]);
#pragma unroll
            for (int mf = 0; mf < 2; mf++) {
                float* c0 = acc[mf * 8 + nf2 * 2];
                float* c1 = acc[mf * 8 + nf2 * 2 + 1];
                mma16816(c0, ah[mf], bh[0], bh[1]);
                mma16816(c0, al[mf], bh[0], bh[1]);
                mma16816(c0, ah[mf], bl[0], bl[1]);
                mma16816(c1, ah[mf], bh[2], bh[3]);
                mma16816(c1, al[mf], bh[2], bh[3]);
                mma16816(c1, ah[mf], bl[2], bl[3]);
            }
        }
    }
    __syncthreads();

    float* sS = (float*)smp;  // [128][132]
    const int g = lane >> 2, c = lane & 3;
    float rsum[4] = {0.f, 0.f, 0.f, 0.f};
#pragma unroll
    for (int mf = 0; mf < 2; mf++)
#pragma unroll
        for (int nf = 0; nf < 8; nf++) {
            float* a = acc[mf * 8 + nf];
            int r0 = wm * 32 + mf * 16 + g, col = wn * 64 + nf * 8 + c * 2;
            float e0 = __expf(a[0]), e1 = __expf(a[1]);
            float e2 = __expf(a[2]), e3 = __expf(a[3]);
            sS[r0 * 132 + col] = e0;       sS[r0 * 132 + col + 1] = e1;
            sS[(r0 + 8) * 132 + col] = e2; sS[(r0 + 8) * 132 + col + 1] = e3;
            rsum[mf * 2] += e0 + e1;
            rsum[mf * 2 + 1] += e2 + e3;
        }
#pragma unroll
    for (int off = 1; off <= 2; off <<= 1)
#pragma unroll
        for (int i = 0; i < 4; i++) rsum[i] += __shfl_xor_sync(0xffffffffu, rsum[i], off);
    if (c == 0) {
#pragma unroll
        for (int mf = 0; mf < 2; mf++)
#pragma unroll
            for (int hh = 0; hh < 2; hh++) {
                int r = wm * 32 + mf * 16 + g + hh * 8;
                g_part[((size_t)n * S + qb + r) * 32 + blockIdx.x * 2 + wn] = rsum[mf * 2 + hh];
            }
    }
    __syncthreads();
    for (int it = tid; it < 4096; it += 256) {
        int row = it >> 5, c4 = it & 31;
        __stcs((float4*)(attn + ((size_t)n * S + qb + row) * S + kb + c4 * 4),
               *(float4*)(sS + row * 132 + c4 * 4));
    }
}

// ---------------------------------------------------------------------------
// K3 helper: normalize E regs -> streaming attn_w store + hi/lo SMEM tiles
// ---------------------------------------------------------------------------
__device__ __forceinline__ void conv_chunk(
    const float4* e, float* attnC, int r0, int u, const float* sInv,
    __nv_bfloat16* Ph, __nv_bfloat16* Pl)
{
#pragma unroll
    for (int i = 0; i < 8; i++) {
        int row = r0 + i * 16;
        float iv = sInv[row];
        float4 v = e[i];
        v.x *= iv; v.y *= iv; v.z *= iv; v.w *= iv;
        __stcs((float4*)(attnC + (size_t)row * S + u * 4), v);
        float ef[4] = {v.x, v.y, v.z, v.w};
        __align__(8) __nv_bfloat16 hb[4], lb[4];
#pragma unroll
        for (int j = 0; j < 4; j++) {
            hb[j] = __float2bfloat16(ef[j]);
            lb[j] = __float2bfloat16(ef[j] - __bfloat162float(hb[j]));
        }
        *(uint2*)(Ph + row * PAD + u * 4) = *(uint2*)hb;
        *(uint2*)(Pl + row * PAD + u * 4) = *(uint2*)lb;
    }
}

// ---------------------------------------------------------------------------
// K3: pipelined AV (reduce folded): prefetch E/V(kc+1) -> MMA(kc) -> convert.
// Emits AO as bf16 hi/lo.
// ---------------------------------------------------------------------------
__global__ __launch_bounds__(256) void av_kernel(float* __restrict__ attn)
{
    extern __shared__ char smp[];
    __nv_bfloat16* sPh = (__nv_bfloat16*)smp;         // [2][128*PAD]
    __nv_bfloat16* sPl = sPh + 2 * 128 * PAD;
    __nv_bfloat16* sVh = sPl + 2 * 128 * PAD;         // [2][64*PAD]
    __nv_bfloat16* sVl = sVh + 2 * 64 * PAD;
    __shared__ float sInv[128];
    const int qb = blockIdx.x * 128, n = blockIdx.y;
    const int tid = threadIdx.x, wid = tid >> 5, lane = tid & 31;
    const int wm = wid >> 1, wn = wid & 1;
    const int r0 = tid >> 4, u = tid & 15;

    if (tid < 128) {
        const float* p = g_part + ((size_t)n * S + qb + tid) * 32;
        float s = 0.f;
#pragma unroll
        for (int i8 = 0; i8 < 8; i8++) {
            float4 v4 = *(const float4*)(p + i8 * 4);
            s = ((((s + v4.x) + v4.y) + v4.z) + v4.w);
        }
        sInv[tid] = 1.f / s;
    }
    __syncthreads();

    float* attnBase = attn + ((size_t)n * S + qb) * S;
    const __nv_bfloat16* Vh = g_Vhi + (size_t)n * DK * S;
    const __nv_bfloat16* Vl = g_Vlo + (size_t)n * DK * S;

    float4 e[8];
#pragma unroll
    for (int i = 0; i < 8; i++)
        e[i] = __ldcs((const float4*)(attnBase + (size_t)(r0 + i * 16) * S + u * 4));
#pragma unroll
    for (int j = 0; j < 2; j++) {
        int idx = tid + j * 256, cc = idx >> 3, uu = idx & 7;
        size_t go = (size_t)cc * S + uu * 8;
        cp16(smem_u32(sVh + cc * PAD + uu * 8), Vh + go);
        cp16(smem_u32(sVl + cc * PAD + uu * 8), Vl + go);
    }
    CP_COMMIT();
    conv_chunk(e, attnBase, r0, u, sInv, sPh, sPl);
    CP_WAIT0();
    __syncthreads();

    float acc[8][4];
#pragma unroll
    for (int f = 0; f < 8; f++)
#pragma unroll
        for (int ee = 0; ee < 4; ee++) acc[f][ee] = 0.f;

    const int arow = wm * 32 + (lane & 15);
    const int acol8 = (lane >> 4) << 3;
    const int brow = wn * 32 + (lane & 7) + ((lane >> 4) << 3);
    const int bcol8 = ((lane >> 3) & 1) << 3;

    for (int kc = 0; kc < 32; kc++) {
        const int buf = kc & 1, nxt = buf ^ 1;
        if (kc < 31) {
            float* aC = attnBase + (kc + 1) * 64;
#pragma unroll
            for (int i = 0; i < 8; i++)
                e[i] = __ldcs((const float4*)(aC + (size_t)(r0 + i * 16) * S + u * 4));
#pragma unroll
            for (int j = 0; j < 2; j++) {
                int idx = tid + j * 256, cc = idx >> 3, uu = idx & 7;
                size_t go = (size_t)cc * S + (kc + 1) * 64 + uu * 8;
                cp16(smem_u32(sVh + nxt * 64 * PAD + cc * PAD + uu * 8), Vh + go);
                cp16(smem_u32(sVl + nxt * 64 * PAD + cc * PAD + uu * 8), Vl + go);
            }
            CP_COMMIT();
        }
        const uint32_t uPh = smem_u32(sPh + buf * 128 * PAD);
        const uint32_t uPl = smem_u32(sPl + buf * 128 * PAD);
        const uint32_t uVh = smem_u32(sVh + buf * 64 * PAD);
        const uint32_t uVl = smem_u32(sVl + buf * 64 * PAD);
#pragma unroll
        for (int ks = 0; ks < 4; ks++) {
            const int k0 = ks * 16;
            uint32_t ah[2][4], al[2][4];
#pragma unroll
            for (int mf = 0; mf < 2; mf++) {
                uint32_t off = (uint32_t)((arow + mf * 16) * PAD + k0 + acol8) * 2;
                ldsm4(uPh + off, ah[mf][0], ah[mf][1], ah[mf][2], ah[mf][3]);
                ldsm4(uPl + off, al[mf][0], al[mf][1], al[mf][2], al[mf][3]);
            }
#pragma unroll
            for (int nf2 = 0; nf2 < 2; nf2++) {
                uint32_t boff = (uint32_t)((brow + nf2 * 16) * PAD + k0 + bcol8) * 2;
                uint32_t bh[4], bl[4];
                ldsm4(uVh + boff, bh[0], bh[1], bh[2], bh[3]);
                ldsm4(uVl + boff, bl[0], bl[1], bl[2], bl[3]);
#pragma unroll
                for (int mf = 0; mf < 2; mf++) {
                    float* c0 = acc[mf * 4 + nf2 * 2];
                    float* c1 = acc[mf * 4 + nf2 * 2 + 1];
                    mma16816(c0, ah[mf], bh[0], bh[1]);
                    mma16816(c0, al[mf], bh[0], bh[1]);
                    mma16816(c0, ah[mf], bl[0], bl[1]);
                    mma16816(c1, ah[mf], bh[2], bh[3]);
                    mma16816(c1, al[mf], bh[2], bh[3]);
                    mma16816(c1, ah[mf], bl[2], bl[3]);
                }
            }
        }
        if (kc < 31) {
            conv_chunk(e, attnBase + (kc + 1) * 64, r0, u, sInv,
                       sPh + nxt * 128 * PAD, sPl + nxt * 128 * PAD);
            CP_WAIT0();
        }
        __syncthreads();
    }

    // scatter O hi/lo into torch-faithful [B,S,DM]
    const int g = lane >> 2, c = lane & 3;
#pragma unroll
    for (int mf = 0; mf < 2; mf++)
#pragma unroll
        for (int nf = 0; nf < 4; nf++) {
            float* a = acc[mf * 4 + nf];
            int col = wn * 32 + nf * 8 + c * 2;
#pragma unroll
            for (int hh = 0; hh < 2; hh++) {
                int q = qb + wm * 32 + mf * 16 + g + hh * 8;
                size_t off = ((size_t)(q >> 9) * S + ((q & 511) << 2) + (n >> 3)) * DM +
                             (n & 7) * 64 + col;
                float v0 = a[hh * 2], v1 = a[hh * 2 + 1];
                __align__(4) __nv_bfloat16 hb[2], lb[2];
                uint32_t hp = hilo_hi(v0, v1, hb);
                lb[0] = __float2bfloat16(v0 - __bfloat162float(hb[0]));
                lb[1] = __float2bfloat16(v1 - __bfloat162float(hb[1]));
                uint32_t lp;
                memcpy(&lp, lb, 4);
                *(uint32_t*)(g_AOh + off) = hp;
                *(uint32_t*)(g_AOl + off) = lp;
            }
        }
}

// ---------------------------------------------------------------------------
// K4: out-projection via mma hi/lo. CTA 64d x 64s; 4 warps (2x2); K=512 in 8.
// ---------------------------------------------------------------------------
__global__ __launch_bounds__(128) void proj_mma_kernel(
    const float* __restrict__ bo, float* __restrict__ Z)
{
    extern __shared__ __nv_bfloat16 smz[];
    __nv_bfloat16* sAh = smz;                  // Wo [64d][PAD]
    __nv_bfloat16* sAl = smz + 64 * PAD;
    __nv_bfloat16* sBh = smz + 128 * PAD;      // AO [64s][PAD]
    __nv_bfloat16* sBl = smz + 192 * PAD;
    const int s0 = blockIdx.x * 64, d0 = blockIdx.y * 64, bp = blockIdx.z;
    const int tid = threadIdx.x, wid = tid >> 5, lane = tid & 31;
    const int wm = wid >> 1, wn = wid & 1;
    const uint32_t uAh = smem_u32(sAh), uAl = smem_u32(sAl);
    const uint32_t uBh = smem_u32(sBh), uBl = smem_u32(sBl);
    const int arow = wm * 32 + (lane & 15);
    const int acol8 = (lane >> 4) << 3;
    const int brow = wn * 32 + (lane & 7) + ((lane >> 4) << 3);
    const int bcol8 = ((lane >> 3) & 1) << 3;

    float acc[2][4][4];
#pragma unroll
    for (int f = 0; f < 2; f++)
#pragma unroll
        for (int nf = 0; nf < 4; nf++)
#pragma unroll
            for (int e = 0; e < 4; e++) acc[f][nf][e] = 0.f;

    const __nv_bfloat16* Woh = g_Wh + 393216;
    const __nv_bfloat16* Wol = g_Wl + 393216;

    for (int mc = 0; mc < 8; mc++) {
        const int m0 = mc * 64;
        for (int u = tid; u < 1024; u += 128) {
            int half = u >> 9, r = (u >> 3) & 63, ch = u & 7;
            cp16(smem_u32((half ? sAl : sAh) + r * PAD + ch * 8),
                 (half ? Wol : Woh) + (size_t)(d0 + r) * DM + m0 + ch * 8);
        }
        for (int u = tid; u < 1024; u += 128) {
            int half = u >> 9, r = (u >> 3) & 63, ch = u & 7;
            cp16(smem_u32((half ? sBl : sBh) + r * PAD + ch * 8),
                 (half ? g_AOl : g_AOh) + ((size_t)bp * S + s0 + r) * DM + m0 + ch * 8);
        }
        CP_COMMIT();
        CP_WAIT0();
        __syncthreads();
#pragma unroll
        for (int ks = 0; ks < 4; ks++) {
            const int k0 = ks * 16;
            uint32_t ah[2][4], al[2][4];
#pragma unroll
            for (int mf = 0; mf < 2; mf++) {
                uint32_t off = (uint32_t)((arow + mf * 16) * PAD + k0 + acol8) * 2;
                ldsm4(uAh + off, ah[mf][0], ah[mf][1], ah[mf][2], ah[mf][3]);
                ldsm4(uAl + off, al[mf][0], al[mf][1], al[mf][2], al[mf][3]);
            }
#pragma unroll
            for (int nf2 = 0; nf2 < 2; nf2++) {
                uint32_t boff = (uint32_t)((brow + nf2 * 16) * PAD + k0 + bcol8) * 2;
                uint32_t bh[4], bl[4];
                ldsm4(uBh + boff, bh[0], bh[1], bh[2], bh[3]);
                ldsm4(uBl + boff, bl[0], bl[1], bl[2], bl[3]);
#pragma unroll
                for (int mf = 0; mf < 2; mf++) {
                    float* c0 = acc[mf][nf2 * 2];
                    float* c1 = acc[mf][nf2 * 2 + 1];
                    mma16816(c0, ah[mf], bh[0], bh[1]);
                    mma16816(c0, al[mf], bh[0], bh[1]);
                    mma16816(c0, ah[mf], bl[0], bl[1]);
                    mma16816(c1, ah[mf], bh[2], bh[3]);
                    mma16816(c1, al[mf], bh[2], bh[3]);
                    mma16816(c1, ah[mf], bl[2], bl[3]);
                }
            }
        }
        __syncthreads();
    }

    const int g = lane >> 2, cq = lane & 3;
#pragma unroll
    for (int mf = 0; mf < 2; mf++)
#pragma unroll
        for (int nf = 0; nf < 4; nf++)
#pragma unroll
            for (int rr = 0; rr < 2; rr++) {
                int d = d0 + wm * 32 + mf * 16 + g + rr * 8;
                float bb = __ldg(bo + d);
                int col = wn * 32 + nf * 8 + cq * 2;
                float2 v;
                v.x = acc[mf][nf][rr * 2] + bb;
                v.y = acc[mf][nf][rr * 2 + 1] + bb;
                *(float2*)(Z + ((size_t)bp * DIN + d) * S + s0 + col) = v;
            }
}

// ---------------------------------------------------------------------------
extern "C" void kernel_launch(void* const* d_in, const int* in_sizes, int n_in,
                              void* d_out, int out_size)
{
    const float* x  = (const float*)d_in[0];
    const float* Wq = (const float*)d_in[1];
    const float* bq = (const float*)d_in[2];
    const float* Wk = (const float*)d_in[3];
    const float* bk = (const float*)d_in[4];
    const float* Wv = (const float*)d_in[5];
    const float* bv = (const float*)d_in[6];
    const float* Wo = (const float*)d_in[7];
    const float* bo = (const float*)d_in[8];
    float* out = (float*)d_out;

    const long long zsz = (long long)NB * DIN * S;
    const long long asz = (long long)NB * H * S * S;
    float* attn;
    if ((long long)out_size >= zsz + asz) {
        attn = out + zsz;
    } else {
        void* p = nullptr;
        cudaGetSymbolAddress(&p, g_scratch);
        attn = (float*)p;
    }

    const int qkv_smem   = 512 * PAD * 2;                    // 73,728 B (FIXED)
    const int score_smem = 4 * 128 * PAD * 2;                // 73,728 B
    const int av_smem    = 2 * (2 * 128 + 2 * 64) * PAD * 2; // 110,592 B
    const int proj_smem  = 256 * PAD * 2;                    // 36,864 B
    cudaFuncSetAttribute(qkv_mma_kernel, cudaFuncAttributeMaxDynamicSharedMemorySize, qkv_smem);
    cudaFuncSetAttribute(score_kernel, cudaFuncAttributeMaxDynamicSharedMemorySize, score_smem);
    cudaFuncSetAttribute(av_kernel, cudaFuncAttributeMaxDynamicSharedMemorySize, av_smem);
    cudaFuncSetAttribute(proj_mma_kernel, cudaFuncAttributeMaxDynamicSharedMemorySize, proj_smem);

    xconv_kernel<<<dim3(S / 32, DIN / 32, NB), 256>>>(x);
    wconv_kernel<<<512, 256>>>(Wq, Wk, Wv, Wo);
    qkv_mma_kernel<<<dim3(S / 64, H, NB), 256, qkv_smem>>>(bq, bk, bv);
    score_kernel<<<dim3(16, 16, BH), 256, score_smem>>>(attn);
    av_kernel<<<dim3(16, BH), 256, av_smem>>>(attn);
    proj_mma_kernel<<<dim3(S / 64, DIN / 64, NB), 128, proj_smem>>>(bo, out);
}

// round 16
// speedup vs baseline: 1.4742x; 1.0536x over previous
#include <cuda_runtime.h>
#include <cuda_bf16.h>
#include <stdint.h>
#include <math.h>

#define S   2048
#define DIN 256
#define DM  512
#define NB  4
#define H   8
#define DK  64
#define BH  32
#define PAD 72

__device__ __nv_bfloat16 g_Qc[(size_t)BH * S * 128];   // [n][s][hi(64)|lo(64)]
__device__ __nv_bfloat16 g_Kc[(size_t)BH * S * 128];
__device__ __nv_bfloat16 g_Vhi[(size_t)BH * DK * S];   // [n][c][s]
__device__ __nv_bfloat16 g_Vlo[(size_t)BH * DK * S];
__device__ float g_part[(size_t)BH * S * 32];
__device__ __nv_bfloat16 g_AOh[(size_t)NB * S * DM];   // attn_out hi/lo [B][S][DM]
__device__ __nv_bfloat16 g_AOl[(size_t)NB * S * DM];
__device__ __nv_bfloat16 g_xth[(size_t)NB * S * DIN];  // x^T hi/lo [b][s][d]
__device__ __nv_bfloat16 g_xtl[(size_t)NB * S * DIN];
__device__ __nv_bfloat16 g_Wh[524288];                 // Wq|Wk|Wv|Wo hi
__device__ __nv_bfloat16 g_Wl[524288];                 // lo
__device__ float g_scratch[(size_t)NB * H * S * S];

__device__ __forceinline__ uint32_t smem_u32(const void* p) {
    uint32_t a;
    asm("{ .reg .u64 t; cvta.to.shared.u64 t, %1; cvt.u32.u64 %0, t; }" : "=r"(a) : "l"(p));
    return a;
}
__device__ __forceinline__ void ldsm4(uint32_t addr, uint32_t& r0, uint32_t& r1,
                                      uint32_t& r2, uint32_t& r3) {
    asm volatile("ldmatrix.sync.aligned.m8n8.x4.shared.b16 {%0,%1,%2,%3}, [%4];"
                 : "=r"(r0), "=r"(r1), "=r"(r2), "=r"(r3) : "r"(addr));
}
__device__ __forceinline__ void mma16816(float* c, const uint32_t* a, uint32_t b0, uint32_t b1) {
    asm volatile(
        "mma.sync.aligned.m16n8k16.row.col.f32.bf16.bf16.f32 "
        "{%0,%1,%2,%3},{%4,%5,%6,%7},{%8,%9},{%0,%1,%2,%3};"
        : "+f"(c[0]), "+f"(c[1]), "+f"(c[2]), "+f"(c[3])
        : "r"(a[0]), "r"(a[1]), "r"(a[2]), "r"(a[3]), "r"(b0), "r"(b1));
}
__device__ __forceinline__ void cp16(uint32_t s, const void* g) {
    asm volatile("cp.async.cg.shared.global [%0], [%1], 16;" :: "r"(s), "l"(g));
}
#define CP_COMMIT() asm volatile("cp.async.commit_group;" ::: "memory")
#define CP_WAIT0()  asm volatile("cp.async.wait_group 0;" ::: "memory")

__device__ __forceinline__ uint32_t hilo_hi(float a, float b, __nv_bfloat16* hs) {
    hs[0] = __float2bfloat16(a);
    hs[1] = __float2bfloat16(b);
    uint32_t r;
    memcpy(&r, hs, 4);
    return r;
}

// ---------------------------------------------------------------------------
// P0a: x [b][d][s] fp32 -> xt hi/lo [b][s][d] bf16 (32x32 smem transpose)
// ---------------------------------------------------------------------------
__global__ __launch_bounds__(256) void xconv_kernel(const float* __restrict__ x)
{
    __shared__ float sT[32][33];
    const int s0 = blockIdx.x * 32, d0 = blockIdx.y * 32, b = blockIdx.z;
    const int c = threadIdx.x & 31, r4 = threadIdx.x >> 5;
#pragma unroll
    for (int i = 0; i < 4; i++) {
        int r = r4 * 4 + i;
        sT[r][c] = x[(size_t)(b * DIN + d0 + r) * S + s0 + c];
    }
    __syncthreads();
    const int sl = threadIdx.x >> 3, dg = (threadIdx.x & 7) * 4;
    __align__(8) __nv_bfloat16 hi[4], lo[4];
#pragma unroll
    for (int j = 0; j < 4; j++) {
        float v = sT[dg + j][sl];
        hi[j] = __float2bfloat16(v);
        lo[j] = __float2bfloat16(v - __bfloat162float(hi[j]));
    }
    size_t off = ((size_t)b * S + s0 + sl) * DIN + d0 + dg;
    *(uint2*)(g_xth + off) = *(uint2*)hi;
    *(uint2*)(g_xtl + off) = *(uint2*)lo;
}

// ---------------------------------------------------------------------------
// P0b: Wq|Wk|Wv|Wo -> hi/lo (each 131072 elems, packed at region*131072)
// ---------------------------------------------------------------------------
__global__ __launch_bounds__(256) void wconv_kernel(
    const float* __restrict__ Wq, const float* __restrict__ Wk,
    const float* __restrict__ Wv, const float* __restrict__ Wo)
{
    int idx = blockIdx.x * 256 + threadIdx.x;   // 0..131071
    int base = idx * 4;
    const float* srcs[4] = {Wq, Wk, Wv, Wo};
    float4 v = *(const float4*)(srcs[base >> 17] + (base & 131071));
    float vf[4] = {v.x, v.y, v.z, v.w};
    __align__(8) __nv_bfloat16 hi[4], lo[4];
#pragma unroll
    for (int j = 0; j < 4; j++) {
        hi[j] = __float2bfloat16(vf[j]);
        lo[j] = __float2bfloat16(vf[j] - __bfloat162float(hi[j]));
    }
    *(uint2*)(g_Wh + base) = *(uint2*)hi;
    *(uint2*)(g_Wl + base) = *(uint2*)lo;
}

// ---------------------------------------------------------------------------
// K1: QKV via mma hi/lo. CTA: 64m (one head) x 64s; 8 warps (4 wm x 2 wn);
// warp 16m x 32s. d=256 in 4 chunks. SMEM: X(128 rows) + W(384 rows) = 512*PAD.
// ---------------------------------------------------------------------------
__global__ __launch_bounds__(256) void qkv_mma_kernel(
    const float* __restrict__ bq, const float* __restrict__ bk,
    const float* __restrict__ bv)
{
    extern __shared__ __nv_bfloat16 smq[];
    __nv_bfloat16* sXh = smq;                 // [64][PAD]
    __nv_bfloat16* sXl = smq + 64 * PAD;
    __nv_bfloat16* sWh = smq + 128 * PAD;     // [3][64][PAD]
    __nv_bfloat16* sWl = smq + 320 * PAD;     // [3][64][PAD]  (total 512*PAD)
    const int s0 = blockIdx.x * 64, h = blockIdx.y, b = blockIdx.z;
    const int n = b * 8 + h, m0 = h * 64;
    const int tid = threadIdx.x, wid = tid >> 5, lane = tid & 31;
    const int wm = wid >> 1, wn = wid & 1;
    const uint32_t uXh = smem_u32(sXh), uXl = smem_u32(sXl);
    const uint32_t uWh = smem_u32(sWh), uWl = smem_u32(sWl);
    const int arow = wm * 16 + (lane & 15);
    const int acol8 = (lane >> 4) << 3;
    const int brow = wn * 32 + (lane & 7) + ((lane >> 4) << 3);
    const int bcol8 = ((lane >> 3) & 1) << 3;

    float acc[3][4][4];
#pragma unroll
    for (int w = 0; w < 3; w++)
#pragma unroll
        for (int f = 0; f < 4; f++)
#pragma unroll
            for (int e = 0; e < 4; e++) acc[w][f][e] = 0.f;

    for (int dc = 0; dc < 4; dc++) {
        const int d0 = dc * 64;
        for (int u = tid; u < 1024; u += 256) {
            int half = u >> 9, r = (u >> 3) & 63, ch = u & 7;
            cp16(smem_u32((half ? sXl : sXh) + r * PAD + ch * 8),
                 (half ? g_xtl : g_xth) + ((size_t)b * S + s0 + r) * DIN + d0 + ch * 8);
        }
        for (int u = tid; u < 3072; u += 256) {
            int w = u >> 10, rest = u & 1023;
            int half = rest >> 9, r = (rest >> 3) & 63, ch = rest & 7;
            cp16(smem_u32((half ? sWl : sWh) + w * 64 * PAD + r * PAD + ch * 8),
                 (half ? g_Wl : g_Wh) + w * 131072 + (size_t)(m0 + r) * DIN + d0 + ch * 8);
        }
        CP_COMMIT();
        CP_WAIT0();
        __syncthreads();
#pragma unroll
        for (int ks = 0; ks < 4; ks++) {
            const int k0 = ks * 16;
            uint32_t bh[2][4], bl[2][4];
#pragma unroll
            for (int nf2 = 0; nf2 < 2; nf2++) {
                uint32_t boff = (uint32_t)((brow + nf2 * 16) * PAD + k0 + bcol8) * 2;
                ldsm4(uXh + boff, bh[nf2][0], bh[nf2][1], bh[nf2][2], bh[nf2][3]);
                ldsm4(uXl + boff, bl[nf2][0], bl[nf2][1], bl[nf2][2], bl[nf2][3]);
            }
#pragma unroll
            for (int w = 0; w < 3; w++) {
                uint32_t aoff = (uint32_t)(w * 64 * PAD + arow * PAD + k0 + acol8) * 2;
                uint32_t ah[4], al[4];
                ldsm4(uWh + aoff, ah[0], ah[1], ah[2], ah[3]);
                ldsm4(uWl + aoff, al[0], al[1], al[2], al[3]);
#pragma unroll
                for (int nf2 = 0; nf2 < 2; nf2++) {
                    float* c0 = acc[w][nf2 * 2];
                    float* c1 = acc[w][nf2 * 2 + 1];
                    mma16816(c0, ah, bh[nf2][0], bh[nf2][1]);
                    mma16816(c0, al, bh[nf2][0], bh[nf2][1]);
                    mma16816(c0, ah, bl[nf2][0], bl[nf2][1]);
                    mma16816(c1, ah, bh[nf2][2], bh[nf2][3]);
                    mma16816(c1, al, bh[nf2][2], bh[nf2][3]);
                    mma16816(c1, ah, bl[nf2][2], bl[nf2][3]);
                }
            }
        }
        __syncthreads();
    }

    const int g = lane >> 2, cq = lane & 3;
    // ---- V (w=2): direct stores into [n][c][s] ----
#pragma unroll
    for (int nf = 0; nf < 4; nf++)
#pragma unroll
        for (int rr = 0; rr < 2; rr++) {
            int row = wm * 16 + g + rr * 8;
            float bb = __ldg(bv + m0 + row);
            int col = wn * 32 + nf * 8 + cq * 2;
            float v0 = acc[2][nf][rr * 2] + bb, v1 = acc[2][nf][rr * 2 + 1] + bb;
            __align__(4) __nv_bfloat16 hb[2], lb[2];
            uint32_t hp = hilo_hi(v0, v1, hb);
            lb[0] = __float2bfloat16(v0 - __bfloat162float(hb[0]));
            lb[1] = __float2bfloat16(v1 - __bfloat162float(hb[1]));
            uint32_t lp;
            memcpy(&lp, lb, 4);
            size_t off = ((size_t)n * DK + row) * S + s0 + col;
            *(uint32_t*)(g_Vhi + off) = hp;
            *(uint32_t*)(g_Vlo + off) = lp;
        }

    // ---- Q (w=0), K (w=1): stage [64s][136] then coalesced 256B-row copy ----
    __nv_bfloat16* sStage = smq;  // aliases X region (8704 elems <= 9216)
    const float* bsrc[2] = {bq, bk};
    __nv_bfloat16* dsts[2] = {g_Qc, g_Kc};
#pragma unroll
    for (int w = 0; w < 2; w++) {
#pragma unroll
        for (int nf = 0; nf < 4; nf++)
#pragma unroll
            for (int rr = 0; rr < 2; rr++) {
                int row = wm * 16 + g + rr * 8;
                float bb = __ldg(bsrc[w] + m0 + row);
                int col = wn * 32 + nf * 8 + cq * 2;
                float v0 = acc[w][nf][rr * 2] + bb, v1 = acc[w][nf][rr * 2 + 1] + bb;
                __nv_bfloat16 h0 = __float2bfloat16(v0);
                __nv_bfloat16 h1 = __float2bfloat16(v1);
                sStage[(col + 0) * 136 + row] = h0;
                sStage[(col + 0) * 136 + 64 + row] =
                    __float2bfloat16(v0 - __bfloat162float(h0));
                sStage[(col + 1) * 136 + row] = h1;
                sStage[(col + 1) * 136 + 64 + row] =
                    __float2bfloat16(v1 - __bfloat162float(h1));
            }
        __syncthreads();
        __nv_bfloat16* dst = dsts[w] + ((size_t)n * S + s0) * 128;
        for (int u = tid; u < 1024; u += 256) {
            int r = u >> 4, ch = u & 15;
            *(uint4*)(dst + r * 128 + ch * 8) = *(uint4*)&sStage[r * 136 + ch * 8];
        }
        __syncthreads();
    }
}

// ---------------------------------------------------------------------------
// K2: scores via mma.sync hi/lo (3 products). Writes exp(S) + partial rowsums.
// ---------------------------------------------------------------------------
__global__ __launch_bounds__(256) void score_kernel(float* __restrict__ attn)
{
    extern __shared__ char smp[];
    __nv_bfloat16* sQh = (__nv_bfloat16*)smp;       // [128][PAD]
    __nv_bfloat16* sQl = sQh + 128 * PAD;
    __nv_bfloat16* sKh = sQl + 128 * PAD;
    __nv_bfloat16* sKl = sKh + 128 * PAD;
    const int kb = blockIdx.x * 128, qb = blockIdx.y * 128, n = blockIdx.z;
    const int tid = threadIdx.x, wid = tid >> 5, lane = tid & 31;
    const int wm = wid >> 1, wn = wid & 1;

    const __nv_bfloat16* Qg = g_Qc + ((size_t)n * S + qb) * 128;
    const __nv_bfloat16* Kg = g_Kc + ((size_t)n * S + kb) * 128;
    for (int u = tid; u < 2048; u += 256) {
        int row = u >> 4, ch = u & 15;
        __nv_bfloat16* dq = (ch < 8 ? sQh : sQl) + row * PAD + (ch & 7) * 8;
        __nv_bfloat16* dk = (ch < 8 ? sKh : sKl) + row * PAD + (ch & 7) * 8;
        cp16(smem_u32(dq), Qg + row * 128 + ch * 8);
        cp16(smem_u32(dk), Kg + row * 128 + ch * 8);
    }
    CP_COMMIT();
    CP_WAIT0();
    __syncthreads();

    float acc[16][4];
#pragma unroll
    for (int f = 0; f < 16; f++)
#pragma unroll
        for (int e = 0; e < 4; e++) acc[f][e] = 0.f;

    const uint32_t uQh = smem_u32(sQh), uQl = smem_u32(sQl);
    const uint32_t uKh = smem_u32(sKh), uKl = smem_u32(sKl);
    const int arow = wm * 32 + (lane & 15);
    const int acol8 = (lane >> 4) << 3;
    const int brow = wn * 64 + (lane & 7) + ((lane >> 4) << 3);
    const int bcol8 = ((lane >> 3) & 1) << 3;

#pragma unroll
    for (int ks = 0; ks < 4; ks++) {
        const int k0 = ks * 16;
        uint32_t ah[2][4], al[2][4];
#pragma unroll
        for (int mf = 0; mf < 2; mf++) {
            uint32_t off = (uint32_t)((arow + mf * 16) * PAD + k0 + acol8) * 2;
            ldsm4(uQh + off, ah[mf][0], ah[mf][1], ah[mf][2], ah[mf][3]);
            ldsm4(uQl + off, al[mf][0], al[mf][1], al[mf][2], al[mf][3]);
        }
#pragma unroll
        for (int nf2 = 0; nf2 < 4; nf2++) {
            uint32_t boff = (uint32_t)((brow + nf2 * 16) * PAD + k0 + bcol8) * 2;
            uint32_t bh[4], bl[4];
            ldsm4(uKh + boff, bh[0], bh[1], bh[2], bh[3]);
            ldsm4(uKl + boff, bl[0], bl[1], bl[2], bl[3]);
#pragma unroll
            for (int mf = 0; mf < 2; mf++) {
                float* c0 = acc[mf * 8 + nf2 * 2];
                float* c1 = acc[mf * 8 + nf2 * 2 + 1];
                mma16816(c0, ah[mf], bh[0], bh[1]);
                mma16816(c0, al[mf], bh[0], bh[1]);
                mma16816(c0, ah[mf], bl[0], bl[1]);
                mma16816(c1, ah[mf], bh[2], bh[3]);
                mma16816(c1, al[mf], bh[2], bh[3]);
                mma16816(c1, ah[mf], bl[2], bl[3]);
            }
        }
    }
    __syncthreads();

    float* sS = (float*)smp;  // [128][132]
    const int g = lane >> 2, c = lane & 3;
    float rsum[4] = {0.f, 0.f, 0.f, 0.f};
#pragma unroll
    for (int mf = 0; mf < 2; mf++)
#pragma unroll
        for (int nf = 0; nf < 8; nf++) {
            float* a = acc[mf * 8 + nf];
            int r0 = wm * 32 + mf * 16 + g, col = wn * 64 + nf * 8 + c * 2;
            float e0 = __expf(a[0]), e1 = __expf(a[1]);
            float e2 = __expf(a[2]), e3 = __expf(a[3]);
            sS[r0 * 132 + col] = e0;       sS[r0 * 132 + col + 1] = e1;
            sS[(r0 + 8) * 132 + col] = e2; sS[(r0 + 8) * 132 + col + 1] = e3;
            rsum[mf * 2] += e0 + e1;
            rsum[mf * 2 + 1] += e2 + e3;
        }
#pragma unroll
    for (int off = 1; off <= 2; off <<= 1)
#pragma unroll
        for (int i = 0; i < 4; i++) rsum[i] += __shfl_xor_sync(0xffffffffu, rsum[i], off);
    if (c == 0) {
#pragma unroll
        for (int mf = 0; mf < 2; mf++)
#pragma unroll
            for (int hh = 0; hh < 2; hh++) {
                int r = wm * 32 + mf * 16 + g + hh * 8;
                g_part[((size_t)n * S + qb + r) * 32 + blockIdx.x * 2 + wn] = rsum[mf * 2 + hh];
            }
    }
    __syncthreads();
    for (int it = tid; it < 4096; it += 256) {
        int row = it >> 5, c4 = it & 31;
        __stcs((float4*)(attn + ((size_t)n * S + qb + row) * S + kb + c4 * 4),
               *(float4*)(sS + row * 132 + c4 * 4));
    }
}

// ---------------------------------------------------------------------------
// K3 helper: normalize E regs -> streaming attn_w store + hi/lo SMEM tiles
// (64-row q-tile variant: 4 chunks of 16 rows)
// ---------------------------------------------------------------------------
__device__ __forceinline__ void conv_chunk(
    const float4* e, float* attnC, int r0, int u, const float* sInv,
    __nv_bfloat16* Ph, __nv_bfloat16* Pl)
{
#pragma unroll
    for (int i = 0; i < 4; i++) {
        int row = r0 + i * 16;
        float iv = sInv[row];
        float4 v = e[i];
        v.x *= iv; v.y *= iv; v.z *= iv; v.w *= iv;
        __stcs((float4*)(attnC + (size_t)row * S + u * 4), v);
        float ef[4] = {v.x, v.y, v.z, v.w};
        __align__(8) __nv_bfloat16 hb[4], lb[4];
#pragma unroll
        for (int j = 0; j < 4; j++) {
            hb[j] = __float2bfloat16(ef[j]);
            lb[j] = __float2bfloat16(ef[j] - __bfloat162float(hb[j]));
        }
        *(uint2*)(Ph + row * PAD + u * 4) = *(uint2*)hb;
        *(uint2*)(Pl + row * PAD + u * 4) = *(uint2*)lb;
    }
}

// ---------------------------------------------------------------------------
// K3: pipelined AV, q-tile 64 (grid 32x32): prefetch E/V(kc+1) -> MMA(kc) ->
// convert. Emits AO as bf16 hi/lo.
// ---------------------------------------------------------------------------
__global__ __launch_bounds__(256) void av_kernel(float* __restrict__ attn)
{
    extern __shared__ char smp[];
    __nv_bfloat16* sPh = (__nv_bfloat16*)smp;         // [2][64*PAD]
    __nv_bfloat16* sPl = sPh + 2 * 64 * PAD;
    __nv_bfloat16* sVh = sPl + 2 * 64 * PAD;          // [2][64*PAD]
    __nv_bfloat16* sVl = sVh + 2 * 64 * PAD;
    __shared__ float sInv[64];
    const int qb = blockIdx.x * 64, n = blockIdx.y;
    const int tid = threadIdx.x, wid = tid >> 5, lane = tid & 31;
    const int wm = wid >> 1, wn = wid & 1;
    const int r0 = tid >> 4, u = tid & 15;

    if (tid < 64) {
        const float* p = g_part + ((size_t)n * S + qb + tid) * 32;
        float s = 0.f;
#pragma unroll
        for (int i8 = 0; i8 < 8; i8++) {
            float4 v4 = *(const float4*)(p + i8 * 4);
            s = ((((s + v4.x) + v4.y) + v4.z) + v4.w);
        }
        sInv[tid] = 1.f / s;
    }
    __syncthreads();

    float* attnBase = attn + ((size_t)n * S + qb) * S;
    const __nv_bfloat16* Vh = g_Vhi + (size_t)n * DK * S;
    const __nv_bfloat16* Vl = g_Vlo + (size_t)n * DK * S;

    float4 e[4];
#pragma unroll
    for (int i = 0; i < 4; i++)
        e[i] = __ldcs((const float4*)(attnBase + (size_t)(r0 + i * 16) * S + u * 4));
#pragma unroll
    for (int j = 0; j < 2; j++) {
        int idx = tid + j * 256, cc = idx >> 3, uu = idx & 7;
        size_t go = (size_t)cc * S + uu * 8;
        cp16(smem_u32(sVh + cc * PAD + uu * 8), Vh + go);
        cp16(smem_u32(sVl + cc * PAD + uu * 8), Vl + go);
    }
    CP_COMMIT();
    conv_chunk(e, attnBase, r0, u, sInv, sPh, sPl);
    CP_WAIT0();
    __syncthreads();

    float acc[4][4];
#pragma unroll
    for (int f = 0; f < 4; f++)
#pragma unroll
        for (int ee = 0; ee < 4; ee++) acc[f][ee] = 0.f;

    const int arow = wm * 16 + (lane & 15);
    const int acol8 = (lane >> 4) << 3;
    const int brow = wn * 32 + (lane & 7) + ((lane >> 4) << 3);
    const int bcol8 = ((lane >> 3) & 1) << 3;

    for (int kc = 0; kc < 32; kc++) {
        const int buf = kc & 1, nxt = buf ^ 1;
        if (kc < 31) {
            float* aC = attnBase + (kc + 1) * 64;
#pragma unroll
            for (int i = 0; i < 4; i++)
                e[i] = __ldcs((const float4*)(aC + (size_t)(r0 + i * 16) * S + u * 4));
#pragma unroll
            for (int j = 0; j < 2; j++) {
                int idx = tid + j * 256, cc = idx >> 3, uu = idx & 7;
                size_t go = (size_t)cc * S + (kc + 1) * 64 + uu * 8;
                cp16(smem_u32(sVh + nxt * 64 * PAD + cc * PAD + uu * 8), Vh + go);
                cp16(smem_u32(sVl + nxt * 64 * PAD + cc * PAD + uu * 8), Vl + go);
            }
            CP_COMMIT();
        }
        const uint32_t uPh = smem_u32(sPh + buf * 64 * PAD);
        const uint32_t uPl = smem_u32(sPl + buf * 64 * PAD);
        const uint32_t uVh = smem_u32(sVh + buf * 64 * PAD);
        const uint32_t uVl = smem_u32(sVl + buf * 64 * PAD);
#pragma unroll
        for (int ks = 0; ks < 4; ks++) {
            const int k0 = ks * 16;
            uint32_t ah[4], al[4];
            uint32_t aoff = (uint32_t)(arow * PAD + k0 + acol8) * 2;
            ldsm4(uPh + aoff, ah[0], ah[1], ah[2], ah[3]);
            ldsm4(uPl + aoff, al[0], al[1], al[2], al[3]);
#pragma unroll
            for (int nf2 = 0; nf2 < 2; nf2++) {
                uint32_t boff = (uint32_t)((brow + nf2 * 16) * PAD + k0 + bcol8) * 2;
                uint32_t bh[4], bl[4];
                ldsm4(uVh + boff, bh[0], bh[1], bh[2], bh[3]);
                ldsm4(uVl + boff, bl[0], bl[1], bl[2], bl[3]);
                float* c0 = acc[nf2 * 2];
                float* c1 = acc[nf2 * 2 + 1];
                mma16816(c0, ah, bh[0], bh[1]);
                mma16816(c0, al, bh[0], bh[1]);
                mma16816(c0, ah, bl[0], bl[1]);
                mma16816(c1, ah, bh[2], bh[3]);
                mma16816(c1, al, bh[2], bh[3]);
                mma16816(c1, ah, bl[2], bl[3]);
            }
        }
        if (kc < 31) {
            conv_chunk(e, attnBase + (kc + 1) * 64, r0, u, sInv,
                       sPh + nxt * 64 * PAD, sPl + nxt * 64 * PAD);
            CP_WAIT0();
        }
        __syncthreads();
    }

    // scatter O hi/lo into torch-faithful [B,S,DM]
    const int g = lane >> 2, c = lane & 3;
#pragma unroll
    for (int nf = 0; nf < 4; nf++) {
        float* a = acc[nf];
        int col = wn * 32 + nf * 8 + c * 2;
#pragma unroll
        for (int hh = 0; hh < 2; hh++) {
            int q = qb + wm * 16 + g + hh * 8;
            size_t off = ((size_t)(q >> 9) * S + ((q & 511) << 2) + (n >> 3)) * DM +
                         (n & 7) * 64 + col;
            float v0 = a[hh * 2], v1 = a[hh * 2 + 1];
            __align__(4) __nv_bfloat16 hb[2], lb[2];
            uint32_t hp = hilo_hi(v0, v1, hb);
            lb[0] = __float2bfloat16(v0 - __bfloat162float(hb[0]));
            lb[1] = __float2bfloat16(v1 - __bfloat162float(hb[1]));
            uint32_t lp;
            memcpy(&lp, lb, 4);
            *(uint32_t*)(g_AOh + off) = hp;
            *(uint32_t*)(g_AOl + off) = lp;
        }
    }
}

// ---------------------------------------------------------------------------
// K4: out-projection via mma hi/lo. CTA 64d x 64s; 4 warps (2x2); K=512 in 8.
// ---------------------------------------------------------------------------
__global__ __launch_bounds__(128) void proj_mma_kernel(
    const float* __restrict__ bo, float* __restrict__ Z)
{
    extern __shared__ __nv_bfloat16 smz[];
    __nv_bfloat16* sAh = smz;                  // Wo [64d][PAD]
    __nv_bfloat16* sAl = smz + 64 * PAD;
    __nv_bfloat16* sBh = smz + 128 * PAD;      // AO [64s][PAD]
    __nv_bfloat16* sBl = smz + 192 * PAD;
    const int s0 = blockIdx.x * 64, d0 = blockIdx.y * 64, bp = blockIdx.z;
    const int tid = threadIdx.x, wid = tid >> 5, lane = tid & 31;
    const int wm = wid >> 1, wn = wid & 1;
    const uint32_t uAh = smem_u32(sAh), uAl = smem_u32(sAl);
    const uint32_t uBh = smem_u32(sBh), uBl = smem_u32(sBl);
    const int arow = wm * 32 + (lane & 15);
    const int acol8 = (lane >> 4) << 3;
    const int brow = wn * 32 + (lane & 7) + ((lane >> 4) << 3);
    const int bcol8 = ((lane >> 3) & 1) << 3;

    float acc[2][4][4];
#pragma unroll
    for (int f = 0; f < 2; f++)
#pragma unroll
        for (int nf = 0; nf < 4; nf++)
#pragma unroll
            for (int e = 0; e < 4; e++) acc[f][nf][e] = 0.f;

    const __nv_bfloat16* Woh = g_Wh + 393216;
    const __nv_bfloat16* Wol = g_Wl + 393216;

    for (int mc = 0; mc < 8; mc++) {
        const int m0 = mc * 64;
        for (int u = tid; u < 1024; u += 128) {
            int half = u >> 9, r = (u >> 3) & 63, ch = u & 7;
            cp16(smem_u32((half ? sAl : sAh) + r * PAD + ch * 8),
                 (half ? Wol : Woh) + (size_t)(d0 + r) * DM + m0 + ch * 8);
        }
        for (int u = tid; u < 1024; u += 128) {
            int half = u >> 9, r = (u >> 3) & 63, ch = u & 7;
            cp16(smem_u32((half ? sBl : sBh) + r * PAD + ch * 8),
                 (half ? g_AOl : g_AOh) + ((size_t)bp * S + s0 + r) * DM + m0 + ch * 8);
        }
        CP_COMMIT();
        CP_WAIT0();
        __syncthreads();
#pragma unroll
        for (int ks = 0; ks < 4; ks++) {
            const int k0 = ks * 16;
            uint32_t ah[2][4], al[2][4];
#pragma unroll
            for (int mf = 0; mf < 2; mf++) {
                uint32_t off = (uint32_t)((arow + mf * 16) * PAD + k0 + acol8) * 2;
                ldsm4(uAh + off, ah[mf][0], ah[mf][1], ah[mf][2], ah[mf][3]);
                ldsm4(uAl + off, al[mf][0], al[mf][1], al[mf][2], al[mf][3]);
            }
#pragma unroll
            for (int nf2 = 0; nf2 < 2; nf2++) {
                uint32_t boff = (uint32_t)((brow + nf2 * 16) * PAD + k0 + bcol8) * 2;
                uint32_t bh[4], bl[4];
                ldsm4(uBh + boff, bh[0], bh[1], bh[2], bh[3]);
                ldsm4(uBl + boff, bl[0], bl[1], bl[2], bl[3]);
#pragma unroll
                for (int mf = 0; mf < 2; mf++) {
                    float* c0 = acc[mf][nf2 * 2];
                    float* c1 = acc[mf][nf2 * 2 + 1];
                    mma16816(c0, ah[mf], bh[0], bh[1]);
                    mma16816(c0, al[mf], bh[0], bh[1]);
                    mma16816(c0, ah[mf], bl[0], bl[1]);
                    mma16816(c1, ah[mf], bh[2], bh[3]);
                    mma16816(c1, al[mf], bh[2], bh[3]);
                    mma16816(c1, ah[mf], bl[2], bl[3]);
                }
            }
        }
        __syncthreads();
    }

    const int g = lane >> 2, cq = lane & 3;
#pragma unroll
    for (int mf = 0; mf < 2; mf++)
#pragma unroll
        for (int nf = 0; nf < 4; nf++)
#pragma unroll
            for (int rr = 0; rr < 2; rr++) {
                int d = d0 + wm * 32 + mf * 16 + g + rr * 8;
                float bb = __ldg(bo + d);
                int col = wn * 32 + nf * 8 + cq * 2;
                float2 v;
                v.x = acc[mf][nf][rr * 2] + bb;
                v.y = acc[mf][nf][rr * 2 + 1] + bb;
                *(float2*)(Z + ((size_t)bp * DIN + d) * S + s0 + col) = v;
            }
}

// ---------------------------------------------------------------------------
extern "C" void kernel_launch(void* const* d_in, const int* in_sizes, int n_in,
                              void* d_out, int out_size)
{
    const float* x  = (const float*)d_in[0];
    const float* Wq = (const float*)d_in[1];
    const float* bq = (const float*)d_in[2];
    const float* Wk = (const float*)d_in[3];
    const float* bk = (const float*)d_in[4];
    const float* Wv = (const float*)d_in[5];
    const float* bv = (const float*)d_in[6];
    const float* Wo = (const float*)d_in[7];
    const float* bo = (const float*)d_in[8];
    float* out = (float*)d_out;

    const long long zsz = (long long)NB * DIN * S;
    const long long asz = (long long)NB * H * S * S;
    float* attn;
    if ((long long)out_size >= zsz + asz) {
        attn = out + zsz;
    } else {
        void* p = nullptr;
        cudaGetSymbolAddress(&p, g_scratch);
        attn = (float*)p;
    }

    const int qkv_smem   = 512 * PAD * 2;                    // 73,728 B
    const int score_smem = 4 * 128 * PAD * 2;                // 73,728 B
    const int av_smem    = 512 * PAD * 2;                    // 73,728 B
    const int proj_smem  = 256 * PAD * 2;                    // 36,864 B
    cudaFuncSetAttribute(qkv_mma_kernel, cudaFuncAttributeMaxDynamicSharedMemorySize, qkv_smem);
    cudaFuncSetAttribute(score_kernel, cudaFuncAttributeMaxDynamicSharedMemorySize, score_smem);
    cudaFuncSetAttribute(av_kernel, cudaFuncAttributeMaxDynamicSharedMemorySize, av_smem);
    cudaFuncSetAttribute(proj_mma_kernel, cudaFuncAttributeMaxDynamicSharedMemorySize, proj_smem);

    xconv_kernel<<<dim3(S / 32, DIN / 32, NB), 256>>>(x);
    wconv_kernel<<<512, 256>>>(Wq, Wk, Wv, Wo);
    qkv_mma_kernel<<<dim3(S / 64, H, NB), 256, qkv_smem>>>(bq, bk, bv);
    score_kernel<<<dim3(16, 16, BH), 256, score_smem>>>(attn);
    av_kernel<<<dim3(32, BH), 256, av_smem>>>(attn);
    proj_mma_kernel<<<dim3(S / 64, DIN / 64, NB), 128, proj_smem>>>(bo, out);
}